// round 12
// baseline (speedup 1.0000x reference)
#include <cuda_runtime.h>
#include <cuda_bf16.h>
#include <cuda_fp16.h>
#include <math.h>
#include <stdint.h>

// ---------------- problem constants ----------------
#define BB 2
#define LL 4096
#define DM 256
#define DIN 1024          // D_INNER
#define GN_ 128           // NGROUPS*D_STATE
#define HH 8              // NHEADS
#define PP 128            // HEADDIM
#define DPROJ 2312        // D_IN_PROJ (logical)
#define DPROJP 2432       // padded to 19*128
#define DCONVCH 1280      // D_INNER + 2*GN
#define ROWS (BB*LL)      // 8192
#define EPS_ 1e-5f

#define NPART 8
#define NPN 16            // n per partition
#define SS 8              // scan superstep (timesteps per pipeline stage)
#define DST 4             // pipeline depth (stages)

// chunked scan
#define NCH 8
#define CLEN (LL / NCH)   // 512
#define NSUPC (CLEN / SS) // 64

// split-K for GEMM2
#define SPLITK 4

// ---------------- scratch (static device allocations) ----------------
__device__ __align__(16) __nv_bfloat16 g_xh[(size_t)ROWS * DM];
__device__ __align__(16) __nv_bfloat16 g_xl[(size_t)ROWS * DM];
__device__ __align__(16) __nv_bfloat16 g_WinT_h[(size_t)DPROJP * DM];
__device__ __align__(16) __nv_bfloat16 g_WinT_l[(size_t)DPROJP * DM];
__device__ __align__(16) __nv_bfloat16 g_WoutT_h[(size_t)DM * DIN];
__device__ __align__(16) __nv_bfloat16 g_WoutT_l[(size_t)DM * DIN];
__device__ __align__(16) __nv_bfloat16 g_yh[(size_t)ROWS * DIN];
__device__ __align__(16) __nv_bfloat16 g_yl[(size_t)ROWS * DIN];
__device__ float g_zx[(size_t)ROWS * DPROJP];
__device__ float g_xconv[(size_t)ROWS * DCONVCH];
__device__ float g_dA[(size_t)ROWS * HH];
__device__ float g_xsh[(size_t)ROWS * PP];
__device__ float g_bh[(size_t)ROWS * HH * GN_];    // B*bscale*dt (33.5 MB)
__device__ __align__(16) __half g_ypart[(size_t)NPART * ROWS * DIN];   // fp16 partials (128 MB)
__device__ __align__(16) float g_opart[(size_t)SPLITK * ROWS * DM];    // GEMM2 split-K partials (32 MB)

typedef unsigned long long ull;
// chunk boundary states: lin = ((ch*NPART+part)*HH+h)*BB+b, ch in 0..NCH-2
__device__ __align__(16) ull g_sf[(NCH - 1) * NPART * HH * BB][8][128];   // 7.3 MB
__device__ float g_aprod[(NCH - 1) * NPART * HH * BB];

// ---------------- small helpers ----------------
__device__ __forceinline__ float siluf(float x) { return x / (1.f + expf(-x)); }

__device__ __forceinline__ void split_bf16(float v, __nv_bfloat16& h, __nv_bfloat16& l) {
    h = __float2bfloat16(v);
    l = __float2bfloat16(v - __bfloat162float(h));
}

__device__ __forceinline__ ull f32x2_fma(ull a, ull b, ull c) {
    ull d; asm("fma.rn.f32x2 %0, %1, %2, %3;" : "=l"(d) : "l"(a), "l"(b), "l"(c)); return d;
}
__device__ __forceinline__ ull f32x2_mul(ull a, ull b) {
    ull d; asm("mul.rn.f32x2 %0, %1, %2;" : "=l"(d) : "l"(a), "l"(b)); return d;
}
__device__ __forceinline__ ull f32x2_pack(float lo, float hi) {
    ull d; asm("mov.b64 %0, {%1, %2};" : "=l"(d) : "f"(lo), "f"(hi)); return d;
}
__device__ __forceinline__ float2 f32x2_unpack(ull v) {
    float2 r; asm("mov.b64 {%0, %1}, %2;" : "=f"(r.x), "=f"(r.y) : "l"(v)); return r;
}

__device__ __forceinline__ uint32_t smem_u32(const void* p) {
    uint32_t a;
    asm("{ .reg .u64 t; cvta.to.shared.u64 t, %1; cvt.u32.u64 %0, t; }" : "=r"(a) : "l"(p));
    return a;
}

// ---------------- async copy helpers ----------------
__device__ __forceinline__ void cp_async16(uint32_t saddr, const void* gptr) {
    asm volatile("cp.async.cg.shared.global [%0], [%1], 16;"
                 :: "r"(saddr), "l"(gptr) : "memory");
}
__device__ __forceinline__ void cp_async4(uint32_t saddr, const void* gptr) {
    asm volatile("cp.async.ca.shared.global [%0], [%1], 4;"
                 :: "r"(saddr), "l"(gptr) : "memory");
}
#define CP_COMMIT() asm volatile("cp.async.commit_group;" ::: "memory")
template <int N> __device__ __forceinline__ void cp_wait() {
    asm volatile("cp.async.wait_group %0;" :: "n"(N) : "memory");
}

__device__ __forceinline__ void ldmatrix_x4(uint32_t* r, uint32_t addr) {
    asm volatile("ldmatrix.sync.aligned.m8n8.x4.shared.b16 {%0,%1,%2,%3}, [%4];"
                 : "=r"(r[0]), "=r"(r[1]), "=r"(r[2]), "=r"(r[3]) : "r"(addr));
}

__device__ __forceinline__ void mma_bf16(float* c, const uint32_t* a, uint32_t b0, uint32_t b1) {
    asm volatile(
        "mma.sync.aligned.m16n8k16.row.col.f32.bf16.bf16.f32 "
        "{%0,%1,%2,%3}, {%4,%5,%6,%7}, {%8,%9}, {%0,%1,%2,%3};"
        : "+f"(c[0]), "+f"(c[1]), "+f"(c[2]), "+f"(c[3])
        : "r"(a[0]), "r"(a[1]), "r"(a[2]), "r"(a[3]), "r"(b0), "r"(b1));
}

// ---------------- 1) LayerNorm -> split bf16 (single-pass, shuffle) ----------------
__global__ void ln_kernel(const float* __restrict__ u,
                          const float* __restrict__ gamma,
                          const float* __restrict__ beta) {
    __shared__ float w1[8], w2[8], bc[2];
    const int row = blockIdx.x, tid = threadIdx.x;
    const int wid = tid >> 5, lane = tid & 31;
    float v = u[(size_t)row * DM + tid];
    float s1 = v, s2 = v * v;
    #pragma unroll
    for (int o = 16; o > 0; o >>= 1) {
        s1 += __shfl_xor_sync(0xffffffffu, s1, o);
        s2 += __shfl_xor_sync(0xffffffffu, s2, o);
    }
    if (lane == 0) { w1[wid] = s1; w2[wid] = s2; }
    __syncthreads();
    if (wid == 0) {
        float a = (lane < 8) ? w1[lane] : 0.f;
        float b = (lane < 8) ? w2[lane] : 0.f;
        #pragma unroll
        for (int o = 4; o > 0; o >>= 1) {
            a += __shfl_xor_sync(0xffffffffu, a, o);
            b += __shfl_xor_sync(0xffffffffu, b, o);
        }
        if (lane == 0) {
            float mu = a * (1.f / 256.f);
            float var = b * (1.f / 256.f) - mu * mu;
            bc[0] = mu;
            bc[1] = rsqrtf(var + EPS_);
        }
    }
    __syncthreads();
    float xn = (v - bc[0]) * bc[1] * gamma[tid] + beta[tid];
    __nv_bfloat16 h, l;
    split_bf16(xn, h, l);
    g_xh[(size_t)row * DM + tid] = h;
    g_xl[(size_t)row * DM + tid] = l;
}

// ---------------- transposes + split of weights (tiled, coalesced) ----------------
__global__ void transpose_win_kernel(const float* __restrict__ W_in) {
    __shared__ float tile[32][33];
    const int tx = threadIdx.x, ty = threadIdx.y;        // 32 x 8
    const int n0 = blockIdx.x * 32, k0 = blockIdx.y * 32;
    #pragma unroll
    for (int dy = 0; dy < 32; dy += 8) {
        const int n = n0 + tx, k = k0 + ty + dy;
        tile[ty + dy][tx] = (n < DPROJ) ? W_in[(size_t)k * DPROJ + n] : 0.f;
    }
    __syncthreads();
    #pragma unroll
    for (int dy = 0; dy < 32; dy += 8) {
        const int n = n0 + ty + dy, k = k0 + tx;
        float v = tile[tx][ty + dy];
        __nv_bfloat16 h, l;
        split_bf16(v, h, l);
        g_WinT_h[(size_t)n * DM + k] = h;
        g_WinT_l[(size_t)n * DM + k] = l;
    }
}

__global__ void transpose_wout_kernel(const float* __restrict__ W_out) {
    __shared__ float tile[32][33];
    const int tx = threadIdx.x, ty = threadIdx.y;        // 32 x 8
    const int n0 = blockIdx.x * 32, k0 = blockIdx.y * 32;
    #pragma unroll
    for (int dy = 0; dy < 32; dy += 8) {
        tile[ty + dy][tx] = W_out[(size_t)(k0 + ty + dy) * DM + n0 + tx];
    }
    __syncthreads();
    #pragma unroll
    for (int dy = 0; dy < 32; dy += 8) {
        const int n = n0 + ty + dy, k = k0 + tx;
        float v = tile[tx][ty + dy];
        __nv_bfloat16 h, l;
        split_bf16(v, h, l);
        g_WoutT_h[(size_t)n * DIN + k] = h;
        g_WoutT_l[(size_t)n * DIN + k] = l;
    }
}

// ---------------- 2) split-bf16 GEMM, interleaved segments, optional split-K ----------------
// blockIdx.z selects K-slice of CPS*32; operand rows have stride Kstride.
// Output plane = C + blockIdx.z * planeStride.
#define STR 40   // smem row stride (bf16): conflict-free for ldmatrix
#define OBUF (128 * STR * 2)          // bytes per operand buffer (10240)
#define STAGE4 (4 * OBUF)             // 40960
#define GEMM_SMEM (2 * STAGE4)        // 81920

template <int CPS>
__global__ void __launch_bounds__(256, 2)
mma_gemm_kernel(const __nv_bfloat16* __restrict__ Ah,
                const __nv_bfloat16* __restrict__ Al,
                const __nv_bfloat16* __restrict__ Bh,
                const __nv_bfloat16* __restrict__ Bl,
                int Kstride,
                float* __restrict__ C, int ldc, size_t planeStride,
                const float* __restrict__ Cadd) {
    extern __shared__ char dsmem[];
    const uint32_t sbase = smem_u32(dsmem);

    const int tid = threadIdx.x;
    const int wid = tid >> 5, lid = tid & 31;
    const int wm = wid >> 2;           // 0..1
    const int wn = wid & 3;            // 0..3
    const int tileRow = blockIdx.y * 128;
    const int tileCol = blockIdx.x * 128;
    const int kbase = blockIdx.z * (CPS * 32);
    C += (size_t)blockIdx.z * planeStride;

    const int stRow = tid & 127;
    const bool stB = tid >= 128;
    const __nv_bfloat16* gH0 = stB ? Bh : Ah;
    const __nv_bfloat16* gL0 = stB ? Bl : Al;
    const size_t gRowOff = (size_t)((stB ? tileCol : tileRow) + stRow) * Kstride + kbase;
    const uint32_t stSmemOff = (stB ? 2u * OBUF : 0u) + (uint32_t)(stRow * STR) * 2;

    const int aRowOff = (lid & 7) + ((lid >> 3) & 1) * 8;
    const int aKOff   = (lid >> 4) * 8;
    const int bNOff   = (lid & 7) + ((lid >> 4) & 1) * 8;
    const int bKOff   = ((lid >> 3) & 1) * 8;

    float acc[4][4][4];
    #pragma unroll
    for (int i = 0; i < 4; ++i)
        #pragma unroll
        for (int j = 0; j < 4; ++j)
            #pragma unroll
            for (int q = 0; q < 4; ++q) acc[i][j][q] = 0.f;

    auto issue = [&](int c) {
        if (c < CPS) {
            const __nv_bfloat16* gh = gH0 + gRowOff + c * 32;
            const __nv_bfloat16* gl = gL0 + gRowOff + c * 32;
            const uint32_t sh = sbase + (uint32_t)(c & 1) * STAGE4 + stSmemOff;
            const uint32_t sl = sh + OBUF;
            cp_async16(sh,      gh);
            cp_async16(sh + 16, gh + 8);
            cp_async16(sh + 32, gh + 16);
            cp_async16(sh + 48, gh + 24);
            cp_async16(sl,      gl);
            cp_async16(sl + 16, gl + 8);
            cp_async16(sl + 32, gl + 16);
            cp_async16(sl + 48, gl + 24);
        }
        CP_COMMIT();
    };

    issue(0);
    for (int c = 0; c < CPS; ++c) {
        cp_wait<0>();
        __syncthreads();
        issue(c + 1);

        const uint32_t base = sbase + (uint32_t)(c & 1) * STAGE4;
        const uint32_t aHB = base;
        const uint32_t aLB = base + OBUF;
        const uint32_t bHB = base + 2u * OBUF;
        const uint32_t bLB = base + 3u * OBUF;

        #pragma unroll
        for (int kk2 = 0; kk2 < 2; ++kk2) {
            const int kk = kk2 * 16;
            uint32_t bh[2][4], bl[2][4];
            #pragma unroll
            for (int pr = 0; pr < 2; ++pr) {
                const uint32_t off = (uint32_t)((wn * 32 + pr * 16 + bNOff) * STR + kk + bKOff) * 2;
                ldmatrix_x4(bh[pr], bHB + off);
                ldmatrix_x4(bl[pr], bLB + off);
            }
            #pragma unroll
            for (int mt = 0; mt < 4; ++mt) {
                const uint32_t aoff = (uint32_t)((wm * 64 + mt * 16 + aRowOff) * STR + kk + aKOff) * 2;
                uint32_t ah[4];
                ldmatrix_x4(ah, aHB + aoff);
                #pragma unroll
                for (int nt = 0; nt < 4; ++nt) {
                    const int hi = (nt & 1) * 2;
                    mma_bf16(acc[mt][nt], ah, bh[nt >> 1][hi], bh[nt >> 1][hi + 1]);
                }
                #pragma unroll
                for (int nt = 0; nt < 4; ++nt) {
                    const int hi = (nt & 1) * 2;
                    mma_bf16(acc[mt][nt], ah, bl[nt >> 1][hi], bl[nt >> 1][hi + 1]);
                }
                uint32_t al[4];
                ldmatrix_x4(al, aLB + aoff);
                #pragma unroll
                for (int nt = 0; nt < 4; ++nt) {
                    const int hi = (nt & 1) * 2;
                    mma_bf16(acc[mt][nt], al, bh[nt >> 1][hi], bh[nt >> 1][hi + 1]);
                }
            }
        }
        __syncthreads();
    }

    const int gID = lid >> 2, qid = lid & 3;
    #pragma unroll
    for (int mt = 0; mt < 4; ++mt) {
        const int r0 = tileRow + wm * 64 + mt * 16 + gID;
        #pragma unroll
        for (int nt = 0; nt < 4; ++nt) {
            const int col = tileCol + wn * 32 + nt * 8 + qid * 2;
            float2 v0 = make_float2(acc[mt][nt][0], acc[mt][nt][1]);
            float2 v1 = make_float2(acc[mt][nt][2], acc[mt][nt][3]);
            if (Cadd) {
                const float2 a0 = *(const float2*)(Cadd + (size_t)r0 * ldc + col);
                const float2 a1 = *(const float2*)(Cadd + (size_t)(r0 + 8) * ldc + col);
                v0.x += a0.x; v0.y += a0.y;
                v1.x += a1.x; v1.y += a1.y;
            }
            *(float2*)(C + (size_t)r0 * ldc + col) = v0;
            *(float2*)(C + (size_t)(r0 + 8) * ldc + col) = v1;
        }
    }
}

// ---------------- 2b) reduce split-K partials + residual u ----------------
__global__ void reduce_out_kernel(const float* __restrict__ u, float* __restrict__ out) {
    const size_t i4 = ((size_t)blockIdx.x * 256 + threadIdx.x) * 4;
    float4 r = *(const float4*)(u + i4);
    #pragma unroll
    for (int s = 0; s < SPLITK; ++s) {
        const float4 p = *(const float4*)(g_opart + (size_t)s * ROWS * DM + i4);
        r.x += p.x; r.y += p.y; r.z += p.z; r.w += p.w;
    }
    *(float4*)(out + i4) = r;
}

// ---------------- 3) causal depthwise conv (K=4) + SiLU, register ring over l ----------------
#define CLT 16
__global__ void conv_kernel(const float* __restrict__ conv_w,
                            const float* __restrict__ conv_b) {
    const int c = blockIdx.x * 256 + threadIdx.x;   // 0..1279 (grid.x = 5)
    const int l0 = blockIdx.y * CLT;
    const int b = blockIdx.z;
    const size_t base = ((size_t)b * LL) * DPROJP + DIN + c;
    const float w0 = conv_w[c * 4 + 0], w1 = conv_w[c * 4 + 1];
    const float w2 = conv_w[c * 4 + 2], w3 = conv_w[c * 4 + 3];
    const float bias = conv_b[c];

    float x0 = 0.f, x1 = 0.f, x2 = 0.f;
    if (l0 > 0) {
        x0 = g_zx[base + (size_t)(l0 - 3) * DPROJP];
        x1 = g_zx[base + (size_t)(l0 - 2) * DPROJP];
        x2 = g_zx[base + (size_t)(l0 - 1) * DPROJP];
    }
    #pragma unroll
    for (int i = 0; i < CLT; ++i) {
        const float x3 = g_zx[base + (size_t)(l0 + i) * DPROJP];
        float acc = fmaf(x0, w0, bias);
        acc = fmaf(x1, w1, acc);
        acc = fmaf(x2, w2, acc);
        acc = fmaf(x3, w3, acc);
        g_xconv[((size_t)b * LL + l0 + i) * DCONVCH + c] = siluf(acc);
        x0 = x1; x1 = x2; x2 = x3;
    }
}

// ---------------- 4) prep: dt/dA + x_shared mean + prescaled B (fused) ----------------
__global__ void prep_kernel(const float* __restrict__ Bscale,
                            const float* __restrict__ dt_bias,
                            const float* __restrict__ A_log) {
    __shared__ float sdt[HH];
    const int row = blockIdx.x, p = threadIdx.x;    // 128 threads
    if (p < HH) {
        float dt = g_zx[(size_t)row * DPROJP + 2304 + p] + dt_bias[p];
        float dtp = (dt > 20.f) ? dt : log1pf(expf(dt));
        sdt[p] = dtp;
        g_dA[row * HH + p] = expf(-expf(A_log[p]) * dtp);
    }
    const float* xrow = g_xconv + (size_t)row * DCONVCH;
    float s = 0.f;
    #pragma unroll
    for (int h = 0; h < HH; ++h) s += xrow[h * PP + p];
    g_xsh[(size_t)row * PP + p] = s * 0.125f;
    __syncthreads();
    const float Bn = xrow[DIN + p];                  // p == n here
    float* dst = g_bh + (size_t)row * (HH * GN_) + p;
    #pragma unroll
    for (int h = 0; h < HH; ++h)
        dst[h * GN_] = Bn * Bscale[h * GN_ + p] * sdt[h];
}

// ---------------- 5a) chunked scan pass 1: state-only per chunk (chunks 0..NCH-2) ----------------
#define SLOT1 152

__global__ void __launch_bounds__(128, 1)
scan_state_kernel() {
    __shared__ __align__(16) float ring[DST][SS][SLOT1];

    const int part = blockIdx.x, h = blockIdx.y;
    const int b = blockIdx.z % BB, ch = blockIdx.z / BB;   // ch in 0..NCH-2
    const int tid = threadIdx.x;                 // = p
    const int n0 = part * NPN;
    const int lane16 = tid & 15;
    const int tgrp = tid >> 4;
    const size_t row0 = (size_t)b * LL + (size_t)ch * CLEN;

    ull state[8];
    #pragma unroll
    for (int j = 0; j < 8; ++j) state[j] = 0ull;

    auto issue = [&](int s) {
        if (s < NSUPC) {
            const size_t row = row0 + (size_t)s * SS + tgrp;
            float* dstT = &ring[s & (DST - 1)][tgrp][0];
            const float* bhrow  = g_bh + (row * HH + h) * GN_ + n0;
            const float* xshrow = g_xsh + row * PP;
            #pragma unroll
            for (int c = lane16; c < 36; c += 16) {
                const float* src;
                float* dst;
                if (c < 4) { src = bhrow + c * 4;        dst = dstT + c * 4; }
                else       { src = xshrow + (c - 4) * 4; dst = dstT + 16 + (c - 4) * 4; }
                cp_async16(smem_u32(dst), src);
            }
            if (lane16 == 8) cp_async4(smem_u32(dstT + 144), g_dA + row * HH + h);
        }
        CP_COMMIT();
    };

    #pragma unroll
    for (int s = 0; s < DST - 1; ++s) issue(s);

    float ap = 1.f;
    for (int s = 0; s < NSUPC; ++s) {
        cp_wait<DST - 2>();
        __syncthreads();

        const float* slotp = &ring[s & (DST - 1)][0][0];
        #pragma unroll
        for (int i = 0; i < SS; ++i) {
            const float* s4 = slotp + i * SLOT1;
            const ull* s8 = (const ull*)s4;
            const float x = s4[16 + tid];
            const float dAv = s4[144];
            const ull dAp = f32x2_pack(dAv, dAv);
            const ull cfp = f32x2_pack(x, x);
            #pragma unroll
            for (int j = 0; j < 8; ++j)
                state[j] = f32x2_fma(dAp, state[j], f32x2_mul(cfp, s8[j]));
            ap *= dAv;
        }
        issue(s + DST - 1);
    }

    const int lin = ((ch * NPART + part) * HH + h) * BB + b;
    #pragma unroll
    for (int j = 0; j < 8; ++j) g_sf[lin][j][tid] = state[j];
    if (tid == 0) g_aprod[lin] = ap;
}

// ---------------- 5b) chunked scan pass 2: full scan per chunk with combined init ----------------
#define SLOTF 168

__global__ void __launch_bounds__(128, 1)
scan_y_kernel() {
    __shared__ __align__(16) float ring[DST][SS][SLOTF];

    const int part = blockIdx.x, h = blockIdx.y;
    const int b = blockIdx.z % BB, ch = blockIdx.z / BB;   // ch in 0..NCH-1
    const int tid = threadIdx.x;                 // = p
    const int n0 = part * NPN;
    const int lane16 = tid & 15;
    const int tgrp = tid >> 4;
    const size_t row0 = (size_t)b * LL + (size_t)ch * CLEN;

    ull state[8];
    #pragma unroll
    for (int j = 0; j < 8; ++j) state[j] = 0ull;
    if (ch > 0) {
        float w = 1.f;
        for (int k = ch - 1; k >= 0; --k) {
            const int lin = ((k * NPART + part) * HH + h) * BB + b;
            const ull wp = f32x2_pack(w, w);
            #pragma unroll
            for (int j = 0; j < 8; ++j)
                state[j] = f32x2_fma(wp, g_sf[lin][j][tid], state[j]);
            w *= g_aprod[lin];
        }
    }

    auto issue = [&](int s) {
        if (s < NSUPC) {
            const size_t row = row0 + (size_t)s * SS + tgrp;
            float* dstT = &ring[s & (DST - 1)][tgrp][0];
            const float* bhrow   = g_bh + (row * HH + h) * GN_ + n0;
            const float* convrow = g_xconv + row * DCONVCH;
            const float* xshrow  = g_xsh + row * PP;
            #pragma unroll
            for (int c = lane16; c < 40; c += 16) {
                const float* src;
                float* dst;
                if (c < 4)      { src = bhrow + c * 4;                           dst = dstT + c * 4; }
                else if (c < 8) { src = convrow + DIN + GN_ + n0 + (c - 4) * 4;  dst = dstT + 16 + (c - 4) * 4; }
                else            { src = xshrow + (c - 8) * 4;                    dst = dstT + 32 + (c - 8) * 4; }
                cp_async16(smem_u32(dst), src);
            }
            if (lane16 == 8) cp_async4(smem_u32(dstT + 160), g_dA + row * HH + h);
        }
        CP_COMMIT();
    };

    #pragma unroll
    for (int s = 0; s < DST - 1; ++s) issue(s);

    __half* yp = g_ypart + ((size_t)part * ROWS + row0) * DIN + (size_t)h * PP + tid;

    for (int s = 0; s < NSUPC; ++s) {
        cp_wait<DST - 2>();
        __syncthreads();

        const float* slotp = &ring[s & (DST - 1)][0][0];
        #pragma unroll
        for (int i = 0; i < SS; ++i) {
            const float* s4 = slotp + i * SLOTF;
            const ull* s8 = (const ull*)s4;
            const float x = s4[32 + tid];
            const float dAv = s4[160];
            const ull dAp = f32x2_pack(dAv, dAv);
            const ull cfp = f32x2_pack(x, x);
            ull accA = 0ull, accB = 0ull;
            #pragma unroll
            for (int j = 0; j < 8; ++j) {
                state[j] = f32x2_fma(dAp, state[j], f32x2_mul(cfp, s8[j]));
                if (j & 1) accB = f32x2_fma(s8[8 + j], state[j], accB);
                else       accA = f32x2_fma(s8[8 + j], state[j], accA);
            }
            float2 a = f32x2_unpack(accA);
            float2 c = f32x2_unpack(accB);
            yp[(size_t)(s * SS + i) * DIN] = __float2half((a.x + a.y) + (c.x + c.y));
        }
        issue(s + DST - 1);
    }
}

// ---------------- 6) combine partials + D*x + gate + RMSNorm -> split bf16 (vectorized) ----------------
__global__ void combine_kernel(const float* __restrict__ D_param,
                               const float* __restrict__ rms_w) {
    const int row = blockIdx.x, tid = threadIdx.x;
    __shared__ float red[256];
    const int c0 = tid * 4;

    float s0 = 0.f, s1 = 0.f, s2 = 0.f, s3 = 0.f;
    #pragma unroll
    for (int part = 0; part < NPART; ++part) {
        uint2 v = *(const uint2*)(g_ypart + ((size_t)part * ROWS + row) * DIN + c0);
        const __half2* hp = (const __half2*)&v;
        float2 f0 = __half22float2(hp[0]);
        float2 f1 = __half22float2(hp[1]);
        s0 += f0.x; s1 += f0.y; s2 += f1.x; s3 += f1.y;
    }
    const float Dh = D_param[c0 >> 7];
    const float4 xs = *(const float4*)(g_xsh + (size_t)row * PP + (c0 & 127));
    s0 = fmaf(Dh, xs.x, s0); s1 = fmaf(Dh, xs.y, s1);
    s2 = fmaf(Dh, xs.z, s2); s3 = fmaf(Dh, xs.w, s3);

    const float4 z = *(const float4*)(g_zx + (size_t)row * DPROJP + c0);
    float y0 = s0 * siluf(z.x), y1 = s1 * siluf(z.y);
    float y2 = s2 * siluf(z.z), y3 = s3 * siluf(z.w);

    red[tid] = y0 * y0 + y1 * y1 + y2 * y2 + y3 * y3;
    __syncthreads();
    #pragma unroll
    for (int s = 128; s > 0; s >>= 1) { if (tid < s) red[tid] += red[tid + s]; __syncthreads(); }
    const float rstd = rsqrtf(red[0] * (1.f / (float)DIN) + EPS_);

    const float4 rw = *(const float4*)(rms_w + c0);
    float v0 = y0 * rstd * rw.x, v1 = y1 * rstd * rw.y;
    float v2 = y2 * rstd * rw.z, v3 = y3 * rstd * rw.w;

    __nv_bfloat16 hv[4], lv[4];
    split_bf16(v0, hv[0], lv[0]); split_bf16(v1, hv[1], lv[1]);
    split_bf16(v2, hv[2], lv[2]); split_bf16(v3, hv[3], lv[3]);
    *(uint2*)(g_yh + (size_t)row * DIN + c0) = *(const uint2*)hv;
    *(uint2*)(g_yl + (size_t)row * DIN + c0) = *(const uint2*)lv;
}

// ---------------- launch ----------------
extern "C" void kernel_launch(void* const* d_in, const int* in_sizes, int n_in,
                              void* d_out, int out_size) {
    const float* u        = (const float*)d_in[0];
    const float* ln_gamma = (const float*)d_in[1];
    const float* ln_beta  = (const float*)d_in[2];
    const float* W_in     = (const float*)d_in[3];
    const float* conv_w   = (const float*)d_in[4];
    const float* conv_b   = (const float*)d_in[5];
    const float* dt_bias  = (const float*)d_in[6];
    const float* A_log    = (const float*)d_in[7];
    const float* D_param  = (const float*)d_in[8];
    const float* B_scale  = (const float*)d_in[9];
    const float* rms_w    = (const float*)d_in[10];
    const float* W_out    = (const float*)d_in[11];
    float* out = (float*)d_out;

    cudaFuncSetAttribute(mma_gemm_kernel<8>,
                         cudaFuncAttributeMaxDynamicSharedMemorySize, GEMM_SMEM);

    __nv_bfloat16 *p_xh, *p_xl, *p_winh, *p_winl, *p_wouth, *p_woutl, *p_yh, *p_yl;
    float *p_zx, *p_opart;
    cudaGetSymbolAddress((void**)&p_xh, g_xh);
    cudaGetSymbolAddress((void**)&p_xl, g_xl);
    cudaGetSymbolAddress((void**)&p_winh, g_WinT_h);
    cudaGetSymbolAddress((void**)&p_winl, g_WinT_l);
    cudaGetSymbolAddress((void**)&p_wouth, g_WoutT_h);
    cudaGetSymbolAddress((void**)&p_woutl, g_WoutT_l);
    cudaGetSymbolAddress((void**)&p_yh, g_yh);
    cudaGetSymbolAddress((void**)&p_yl, g_yl);
    cudaGetSymbolAddress((void**)&p_zx, g_zx);
    cudaGetSymbolAddress((void**)&p_opart, g_opart);

    ln_kernel<<<ROWS, 256>>>(u, ln_gamma, ln_beta);
    transpose_win_kernel<<<dim3(DPROJP / 32, DM / 32), dim3(32, 8)>>>(W_in);
    transpose_wout_kernel<<<dim3(DM / 32, DIN / 32), dim3(32, 8)>>>(W_out);

    // GEMM1: zx[8192 x 2432(pad)] = xn @ W_in  (split-bf16 HMMA)
    mma_gemm_kernel<8><<<dim3(DPROJP / 128, ROWS / 128, 1), 256, GEMM_SMEM>>>(
        p_xh, p_xl, p_winh, p_winl, DM, p_zx, DPROJP, 0, nullptr);

    conv_kernel<<<dim3(DCONVCH / 256, LL / CLT, BB), 256>>>(conv_w, conv_b);
    prep_kernel<<<ROWS, 128>>>(B_scale, dt_bias, A_log);

    // chunked scan
    scan_state_kernel<<<dim3(NPART, HH, BB * (NCH - 1)), 128>>>();
    scan_y_kernel<<<dim3(NPART, HH, BB * NCH), 128>>>();

    combine_kernel<<<ROWS, 256>>>(D_param, rms_w);

    // GEMM2 split-K: partials over K slices of 256, then reduce with residual u
    mma_gemm_kernel<8><<<dim3(DM / 128, ROWS / 128, SPLITK), 256, GEMM_SMEM>>>(
        p_yh, p_yl, p_wouth, p_woutl, DIN, p_opart, DM, (size_t)ROWS * DM, nullptr);
    reduce_out_kernel<<<(ROWS * DM) / 1024, 256>>>(u, out);
}

// round 13
// speedup vs baseline: 1.0211x; 1.0211x over previous
#include <cuda_runtime.h>
#include <cuda_bf16.h>
#include <cuda_fp16.h>
#include <math.h>
#include <stdint.h>

// ---------------- problem constants ----------------
#define BB 2
#define LL 4096
#define DM 256
#define DIN 1024          // D_INNER
#define GN_ 128           // NGROUPS*D_STATE
#define HH 8              // NHEADS
#define PP 128            // HEADDIM
#define DPROJ 2312        // D_IN_PROJ (logical)
#define DPROJP 2432       // padded to 19*128
#define DCONVCH 1280      // D_INNER + 2*GN
#define ROWS (BB*LL)      // 8192
#define EPS_ 1e-5f

#define NPART 2
#define NPN 64            // n per partition
#define SS 8              // scan superstep (timesteps per pipeline stage)
#define DST 4             // pipeline depth (stages)

// chunked scan
#define NCH 8
#define CLEN (LL / NCH)   // 512
#define NSUPC (CLEN / SS) // 64

// ---------------- scratch (static device allocations) ----------------
__device__ __align__(16) __nv_bfloat16 g_xh[(size_t)ROWS * DM];
__device__ __align__(16) __nv_bfloat16 g_xl[(size_t)ROWS * DM];
__device__ __align__(16) __nv_bfloat16 g_WinT_h[(size_t)DPROJP * DM];
__device__ __align__(16) __nv_bfloat16 g_WinT_l[(size_t)DPROJP * DM];
__device__ __align__(16) __nv_bfloat16 g_WoutT_h[(size_t)DM * DIN];
__device__ __align__(16) __nv_bfloat16 g_WoutT_l[(size_t)DM * DIN];
__device__ __align__(16) __nv_bfloat16 g_yh[(size_t)ROWS * DIN];
__device__ __align__(16) __nv_bfloat16 g_yl[(size_t)ROWS * DIN];
__device__ float g_zx[(size_t)ROWS * DPROJP];
__device__ float g_xconv[(size_t)ROWS * DCONVCH];
__device__ float g_dA[(size_t)ROWS * HH];
__device__ float g_xsh[(size_t)ROWS * PP];
__device__ float g_bh[(size_t)ROWS * HH * GN_];    // B*bscale*dt (33.5 MB)
__device__ __align__(16) __half g_ypart[(size_t)NPART * ROWS * DIN];   // fp16 partials (32 MB)

typedef unsigned long long ull;
// chunk boundary states: lin = ((ch*NPART+part)*HH+h)*BB+b, ch in 0..NCH-2
__device__ __align__(16) ull g_sf[(NCH - 1) * NPART * HH * BB][32][128];   // 7.3 MB
__device__ float g_aprod[(NCH - 1) * NPART * HH * BB];

// ---------------- small helpers ----------------
__device__ __forceinline__ float siluf(float x) { return x / (1.f + expf(-x)); }

__device__ __forceinline__ void split_bf16(float v, __nv_bfloat16& h, __nv_bfloat16& l) {
    h = __float2bfloat16(v);
    l = __float2bfloat16(v - __bfloat162float(h));
}

__device__ __forceinline__ ull f32x2_fma(ull a, ull b, ull c) {
    ull d; asm("fma.rn.f32x2 %0, %1, %2, %3;" : "=l"(d) : "l"(a), "l"(b), "l"(c)); return d;
}
__device__ __forceinline__ ull f32x2_mul(ull a, ull b) {
    ull d; asm("mul.rn.f32x2 %0, %1, %2;" : "=l"(d) : "l"(a), "l"(b)); return d;
}
__device__ __forceinline__ ull f32x2_pack(float lo, float hi) {
    ull d; asm("mov.b64 %0, {%1, %2};" : "=l"(d) : "f"(lo), "f"(hi)); return d;
}
__device__ __forceinline__ float2 f32x2_unpack(ull v) {
    float2 r; asm("mov.b64 {%0, %1}, %2;" : "=f"(r.x), "=f"(r.y) : "l"(v)); return r;
}

__device__ __forceinline__ uint32_t smem_u32(const void* p) {
    uint32_t a;
    asm("{ .reg .u64 t; cvta.to.shared.u64 t, %1; cvt.u32.u64 %0, t; }" : "=r"(a) : "l"(p));
    return a;
}

// ---------------- async copy helpers ----------------
__device__ __forceinline__ void cp_async16(uint32_t saddr, const void* gptr) {
    asm volatile("cp.async.cg.shared.global [%0], [%1], 16;"
                 :: "r"(saddr), "l"(gptr) : "memory");
}
__device__ __forceinline__ void cp_async4(uint32_t saddr, const void* gptr) {
    asm volatile("cp.async.ca.shared.global [%0], [%1], 4;"
                 :: "r"(saddr), "l"(gptr) : "memory");
}
#define CP_COMMIT() asm volatile("cp.async.commit_group;" ::: "memory")
template <int N> __device__ __forceinline__ void cp_wait() {
    asm volatile("cp.async.wait_group %0;" :: "n"(N) : "memory");
}

__device__ __forceinline__ void ldmatrix_x4(uint32_t* r, uint32_t addr) {
    asm volatile("ldmatrix.sync.aligned.m8n8.x4.shared.b16 {%0,%1,%2,%3}, [%4];"
                 : "=r"(r[0]), "=r"(r[1]), "=r"(r[2]), "=r"(r[3]) : "r"(addr));
}

__device__ __forceinline__ void mma_bf16(float* c, const uint32_t* a, uint32_t b0, uint32_t b1) {
    asm volatile(
        "mma.sync.aligned.m16n8k16.row.col.f32.bf16.bf16.f32 "
        "{%0,%1,%2,%3}, {%4,%5,%6,%7}, {%8,%9}, {%0,%1,%2,%3};"
        : "+f"(c[0]), "+f"(c[1]), "+f"(c[2]), "+f"(c[3])
        : "r"(a[0]), "r"(a[1]), "r"(a[2]), "r"(a[3]), "r"(b0), "r"(b1));
}

// ---------------- 1) LayerNorm -> split bf16 (single-pass, shuffle) ----------------
__global__ void ln_kernel(const float* __restrict__ u,
                          const float* __restrict__ gamma,
                          const float* __restrict__ beta) {
    __shared__ float w1[8], w2[8], bc[2];
    const int row = blockIdx.x, tid = threadIdx.x;
    const int wid = tid >> 5, lane = tid & 31;
    float v = u[(size_t)row * DM + tid];
    float s1 = v, s2 = v * v;
    #pragma unroll
    for (int o = 16; o > 0; o >>= 1) {
        s1 += __shfl_xor_sync(0xffffffffu, s1, o);
        s2 += __shfl_xor_sync(0xffffffffu, s2, o);
    }
    if (lane == 0) { w1[wid] = s1; w2[wid] = s2; }
    __syncthreads();
    if (wid == 0) {
        float a = (lane < 8) ? w1[lane] : 0.f;
        float b = (lane < 8) ? w2[lane] : 0.f;
        #pragma unroll
        for (int o = 4; o > 0; o >>= 1) {
            a += __shfl_xor_sync(0xffffffffu, a, o);
            b += __shfl_xor_sync(0xffffffffu, b, o);
        }
        if (lane == 0) {
            float mu = a * (1.f / 256.f);
            float var = b * (1.f / 256.f) - mu * mu;
            bc[0] = mu;
            bc[1] = rsqrtf(var + EPS_);
        }
    }
    __syncthreads();
    float xn = (v - bc[0]) * bc[1] * gamma[tid] + beta[tid];
    __nv_bfloat16 h, l;
    split_bf16(xn, h, l);
    g_xh[(size_t)row * DM + tid] = h;
    g_xl[(size_t)row * DM + tid] = l;
}

// ---------------- transposes + split of weights (tiled, coalesced) ----------------
__global__ void transpose_win_kernel(const float* __restrict__ W_in) {
    __shared__ float tile[32][33];
    const int tx = threadIdx.x, ty = threadIdx.y;        // 32 x 8
    const int n0 = blockIdx.x * 32, k0 = blockIdx.y * 32;
    #pragma unroll
    for (int dy = 0; dy < 32; dy += 8) {
        const int n = n0 + tx, k = k0 + ty + dy;
        tile[ty + dy][tx] = (n < DPROJ) ? W_in[(size_t)k * DPROJ + n] : 0.f;
    }
    __syncthreads();
    #pragma unroll
    for (int dy = 0; dy < 32; dy += 8) {
        const int n = n0 + ty + dy, k = k0 + tx;
        float v = tile[tx][ty + dy];
        __nv_bfloat16 h, l;
        split_bf16(v, h, l);
        g_WinT_h[(size_t)n * DM + k] = h;
        g_WinT_l[(size_t)n * DM + k] = l;
    }
}

__global__ void transpose_wout_kernel(const float* __restrict__ W_out) {
    __shared__ float tile[32][33];
    const int tx = threadIdx.x, ty = threadIdx.y;        // 32 x 8
    const int n0 = blockIdx.x * 32, k0 = blockIdx.y * 32;
    #pragma unroll
    for (int dy = 0; dy < 32; dy += 8) {
        tile[ty + dy][tx] = W_out[(size_t)(k0 + ty + dy) * DM + n0 + tx];
    }
    __syncthreads();
    #pragma unroll
    for (int dy = 0; dy < 32; dy += 8) {
        const int n = n0 + ty + dy, k = k0 + tx;
        float v = tile[tx][ty + dy];
        __nv_bfloat16 h, l;
        split_bf16(v, h, l);
        g_WoutT_h[(size_t)n * DIN + k] = h;
        g_WoutT_l[(size_t)n * DIN + k] = l;
    }
}

// ---------------- 2) split-bf16 GEMM, interleaved segments ----------------
#define STR 40   // smem row stride (bf16): conflict-free for ldmatrix
#define OBUF (128 * STR * 2)          // bytes per operand buffer (10240)
#define STAGE4 (4 * OBUF)             // 40960
#define GEMM_SMEM (2 * STAGE4)        // 81920

template <int CPS>
__global__ void __launch_bounds__(256, 2)
mma_gemm_kernel(const __nv_bfloat16* __restrict__ Ah,
                const __nv_bfloat16* __restrict__ Al,
                const __nv_bfloat16* __restrict__ Bh,
                const __nv_bfloat16* __restrict__ Bl,
                float* __restrict__ C, int ldc,
                const float* __restrict__ Cadd) {
    constexpr int Kin = CPS * 32;
    extern __shared__ char dsmem[];
    const uint32_t sbase = smem_u32(dsmem);

    const int tid = threadIdx.x;
    const int wid = tid >> 5, lid = tid & 31;
    const int wm = wid >> 2;           // 0..1
    const int wn = wid & 3;            // 0..3
    const int tileRow = blockIdx.y * 128;
    const int tileCol = blockIdx.x * 128;

    const int stRow = tid & 127;
    const bool stB = tid >= 128;
    const __nv_bfloat16* gH0 = stB ? Bh : Ah;
    const __nv_bfloat16* gL0 = stB ? Bl : Al;
    const size_t gRowOff = (size_t)((stB ? tileCol : tileRow) + stRow) * Kin;
    const uint32_t stSmemOff = (stB ? 2u * OBUF : 0u) + (uint32_t)(stRow * STR) * 2;

    const int aRowOff = (lid & 7) + ((lid >> 3) & 1) * 8;
    const int aKOff   = (lid >> 4) * 8;
    const int bNOff   = (lid & 7) + ((lid >> 4) & 1) * 8;
    const int bKOff   = ((lid >> 3) & 1) * 8;

    float acc[4][4][4];
    #pragma unroll
    for (int i = 0; i < 4; ++i)
        #pragma unroll
        for (int j = 0; j < 4; ++j)
            #pragma unroll
            for (int q = 0; q < 4; ++q) acc[i][j][q] = 0.f;

    auto issue = [&](int c) {
        if (c < CPS) {
            const __nv_bfloat16* gh = gH0 + gRowOff + c * 32;
            const __nv_bfloat16* gl = gL0 + gRowOff + c * 32;
            const uint32_t sh = sbase + (uint32_t)(c & 1) * STAGE4 + stSmemOff;
            const uint32_t sl = sh + OBUF;
            cp_async16(sh,      gh);
            cp_async16(sh + 16, gh + 8);
            cp_async16(sh + 32, gh + 16);
            cp_async16(sh + 48, gh + 24);
            cp_async16(sl,      gl);
            cp_async16(sl + 16, gl + 8);
            cp_async16(sl + 32, gl + 16);
            cp_async16(sl + 48, gl + 24);
        }
        CP_COMMIT();
    };

    issue(0);
    for (int c = 0; c < CPS; ++c) {
        cp_wait<0>();
        __syncthreads();
        issue(c + 1);

        const uint32_t base = sbase + (uint32_t)(c & 1) * STAGE4;
        const uint32_t aHB = base;
        const uint32_t aLB = base + OBUF;
        const uint32_t bHB = base + 2u * OBUF;
        const uint32_t bLB = base + 3u * OBUF;

        #pragma unroll
        for (int kk2 = 0; kk2 < 2; ++kk2) {
            const int kk = kk2 * 16;
            uint32_t bh[2][4], bl[2][4];
            #pragma unroll
            for (int pr = 0; pr < 2; ++pr) {
                const uint32_t off = (uint32_t)((wn * 32 + pr * 16 + bNOff) * STR + kk + bKOff) * 2;
                ldmatrix_x4(bh[pr], bHB + off);
                ldmatrix_x4(bl[pr], bLB + off);
            }
            #pragma unroll
            for (int mt = 0; mt < 4; ++mt) {
                const uint32_t aoff = (uint32_t)((wm * 64 + mt * 16 + aRowOff) * STR + kk + aKOff) * 2;
                uint32_t ah[4];
                ldmatrix_x4(ah, aHB + aoff);
                #pragma unroll
                for (int nt = 0; nt < 4; ++nt) {
                    const int hi = (nt & 1) * 2;
                    mma_bf16(acc[mt][nt], ah, bh[nt >> 1][hi], bh[nt >> 1][hi + 1]);
                }
                #pragma unroll
                for (int nt = 0; nt < 4; ++nt) {
                    const int hi = (nt & 1) * 2;
                    mma_bf16(acc[mt][nt], ah, bl[nt >> 1][hi], bl[nt >> 1][hi + 1]);
                }
                uint32_t al[4];
                ldmatrix_x4(al, aLB + aoff);
                #pragma unroll
                for (int nt = 0; nt < 4; ++nt) {
                    const int hi = (nt & 1) * 2;
                    mma_bf16(acc[mt][nt], al, bh[nt >> 1][hi], bh[nt >> 1][hi + 1]);
                }
            }
        }
        __syncthreads();
    }

    const int gID = lid >> 2, qid = lid & 3;
    #pragma unroll
    for (int mt = 0; mt < 4; ++mt) {
        const int r0 = tileRow + wm * 64 + mt * 16 + gID;
        #pragma unroll
        for (int nt = 0; nt < 4; ++nt) {
            const int col = tileCol + wn * 32 + nt * 8 + qid * 2;
            float2 v0 = make_float2(acc[mt][nt][0], acc[mt][nt][1]);
            float2 v1 = make_float2(acc[mt][nt][2], acc[mt][nt][3]);
            if (Cadd) {
                const float2 a0 = *(const float2*)(Cadd + (size_t)r0 * ldc + col);
                const float2 a1 = *(const float2*)(Cadd + (size_t)(r0 + 8) * ldc + col);
                v0.x += a0.x; v0.y += a0.y;
                v1.x += a1.x; v1.y += a1.y;
            }
            *(float2*)(C + (size_t)r0 * ldc + col) = v0;
            *(float2*)(C + (size_t)(r0 + 8) * ldc + col) = v1;
        }
    }
}

// ---------------- 3) causal depthwise conv (K=4) + SiLU, register ring over l ----------------
#define CLT 16
__global__ void conv_kernel(const float* __restrict__ conv_w,
                            const float* __restrict__ conv_b) {
    const int c = blockIdx.x * 256 + threadIdx.x;   // 0..1279 (grid.x = 5)
    const int l0 = blockIdx.y * CLT;
    const int b = blockIdx.z;
    const size_t base = ((size_t)b * LL) * DPROJP + DIN + c;
    const float w0 = conv_w[c * 4 + 0], w1 = conv_w[c * 4 + 1];
    const float w2 = conv_w[c * 4 + 2], w3 = conv_w[c * 4 + 3];
    const float bias = conv_b[c];

    float x0 = 0.f, x1 = 0.f, x2 = 0.f;
    if (l0 > 0) {
        x0 = g_zx[base + (size_t)(l0 - 3) * DPROJP];
        x1 = g_zx[base + (size_t)(l0 - 2) * DPROJP];
        x2 = g_zx[base + (size_t)(l0 - 1) * DPROJP];
    }
    #pragma unroll
    for (int i = 0; i < CLT; ++i) {
        const float x3 = g_zx[base + (size_t)(l0 + i) * DPROJP];
        float acc = fmaf(x0, w0, bias);
        acc = fmaf(x1, w1, acc);
        acc = fmaf(x2, w2, acc);
        acc = fmaf(x3, w3, acc);
        g_xconv[((size_t)b * LL + l0 + i) * DCONVCH + c] = siluf(acc);
        x0 = x1; x1 = x2; x2 = x3;
    }
}

// ---------------- 4) prep: dt/dA + x_shared mean + prescaled B (fused) ----------------
__global__ void prep_kernel(const float* __restrict__ Bscale,
                            const float* __restrict__ dt_bias,
                            const float* __restrict__ A_log) {
    __shared__ float sdt[HH];
    const int row = blockIdx.x, p = threadIdx.x;    // 128 threads
    if (p < HH) {
        float dt = g_zx[(size_t)row * DPROJP + 2304 + p] + dt_bias[p];
        float dtp = (dt > 20.f) ? dt : log1pf(expf(dt));
        sdt[p] = dtp;
        g_dA[row * HH + p] = expf(-expf(A_log[p]) * dtp);
    }
    const float* xrow = g_xconv + (size_t)row * DCONVCH;
    float s = 0.f;
    #pragma unroll
    for (int h = 0; h < HH; ++h) s += xrow[h * PP + p];
    g_xsh[(size_t)row * PP + p] = s * 0.125f;
    __syncthreads();
    const float Bn = xrow[DIN + p];                  // p == n here
    float* dst = g_bh + (size_t)row * (HH * GN_) + p;
    #pragma unroll
    for (int h = 0; h < HH; ++h)
        dst[h * GN_] = Bn * Bscale[h * GN_ + p] * sdt[h];
}

// ---------------- 5a) chunked scan pass 1: state-only per chunk (chunks 0..NCH-2) ----------------
// slot: [0:64) bh, [64:192) xsh, [192] dA, pad to 200
#define SLOT1 200

__global__ void __launch_bounds__(128, 1)
scan_state_kernel() {
    __shared__ __align__(16) float ring[DST][SS][SLOT1];

    const int part = blockIdx.x, h = blockIdx.y;
    const int b = blockIdx.z % BB, ch = blockIdx.z / BB;   // ch in 0..NCH-2
    const int tid = threadIdx.x;                 // = p
    const int n0 = part * NPN;
    const int lane16 = tid & 15;
    const int tgrp = tid >> 4;
    const size_t row0 = (size_t)b * LL + (size_t)ch * CLEN;

    ull state[32];
    #pragma unroll
    for (int j = 0; j < 32; ++j) state[j] = 0ull;

    auto issue = [&](int s) {
        if (s < NSUPC) {
            const size_t row = row0 + (size_t)s * SS + tgrp;
            float* dstT = &ring[s & (DST - 1)][tgrp][0];
            const float* bhrow  = g_bh + (row * HH + h) * GN_ + n0;
            const float* xshrow = g_xsh + row * PP;
            #pragma unroll
            for (int c = lane16; c < 48; c += 16) {
                const float* src;
                float* dst;
                if (c < 16) { src = bhrow + c * 4;         dst = dstT + c * 4; }
                else        { src = xshrow + (c - 16) * 4; dst = dstT + 64 + (c - 16) * 4; }
                cp_async16(smem_u32(dst), src);
            }
            if (lane16 == 8) cp_async4(smem_u32(dstT + 192), g_dA + row * HH + h);
        }
        CP_COMMIT();
    };

    #pragma unroll
    for (int s = 0; s < DST - 1; ++s) issue(s);

    float ap = 1.f;
    for (int s = 0; s < NSUPC; ++s) {
        cp_wait<DST - 2>();
        __syncthreads();

        const float* slotp = &ring[s & (DST - 1)][0][0];
        #pragma unroll
        for (int i = 0; i < SS; ++i) {
            const float* s4 = slotp + i * SLOT1;
            const ull* s8 = (const ull*)s4;       // [0:32) = bh pairs
            const float x = s4[64 + tid];
            const float dAv = s4[192];
            const ull dAp = f32x2_pack(dAv, dAv);
            const ull cfp = f32x2_pack(x, x);
            #pragma unroll
            for (int j = 0; j < 32; ++j)
                state[j] = f32x2_fma(dAp, state[j], f32x2_mul(cfp, s8[j]));
            ap *= dAv;
        }
        issue(s + DST - 1);
    }

    const int lin = ((ch * NPART + part) * HH + h) * BB + b;
    #pragma unroll
    for (int j = 0; j < 32; ++j) g_sf[lin][j][tid] = state[j];
    if (tid == 0) g_aprod[lin] = ap;
}

// ---------------- 5b) chunked scan pass 2: full scan per chunk with combined init ----------------
// slot (264 floats): [0:64) bh, [64:128) C, [128:256) xsh, [256] dA, pad to 264
#define SLOTF 264

__global__ void __launch_bounds__(128, 1)
scan_y_kernel() {
    __shared__ __align__(16) float ring[DST][SS][SLOTF];

    const int part = blockIdx.x, h = blockIdx.y;
    const int b = blockIdx.z % BB, ch = blockIdx.z / BB;   // ch in 0..NCH-1
    const int tid = threadIdx.x;                 // = p
    const int n0 = part * NPN;
    const int lane16 = tid & 15;
    const int tgrp = tid >> 4;
    const size_t row0 = (size_t)b * LL + (size_t)ch * CLEN;

    ull state[32];
    #pragma unroll
    for (int j = 0; j < 32; ++j) state[j] = 0ull;
    if (ch > 0) {
        float w = 1.f;
        for (int k = ch - 1; k >= 0; --k) {
            const int lin = ((k * NPART + part) * HH + h) * BB + b;
            const ull wp = f32x2_pack(w, w);
            #pragma unroll
            for (int j = 0; j < 32; ++j)
                state[j] = f32x2_fma(wp, g_sf[lin][j][tid], state[j]);
            w *= g_aprod[lin];
        }
    }

    auto issue = [&](int s) {
        if (s < NSUPC) {
            const size_t row = row0 + (size_t)s * SS + tgrp;
            float* dstT = &ring[s & (DST - 1)][tgrp][0];
            const float* bhrow   = g_bh + (row * HH + h) * GN_ + n0;
            const float* convrow = g_xconv + row * DCONVCH;
            const float* xshrow  = g_xsh + row * PP;
            #pragma unroll
            for (int c = lane16; c < 64; c += 16) {
                const float* src;
                float* dst;
                if (c < 16)      { src = bhrow + c * 4;                            dst = dstT + c * 4; }
                else if (c < 32) { src = convrow + DIN + GN_ + n0 + (c - 16) * 4;  dst = dstT + 64 + (c - 16) * 4; }
                else             { src = xshrow + (c - 32) * 4;                    dst = dstT + 128 + (c - 32) * 4; }
                cp_async16(smem_u32(dst), src);
            }
            if (lane16 == 8) cp_async4(smem_u32(dstT + 256), g_dA + row * HH + h);
        }
        CP_COMMIT();
    };

    #pragma unroll
    for (int s = 0; s < DST - 1; ++s) issue(s);

    __half* yp = g_ypart + ((size_t)part * ROWS + row0) * DIN + (size_t)h * PP + tid;

    for (int s = 0; s < NSUPC; ++s) {
        cp_wait<DST - 2>();
        __syncthreads();

        const float* slotp = &ring[s & (DST - 1)][0][0];
        #pragma unroll
        for (int i = 0; i < SS; ++i) {
            const float* s4 = slotp + i * SLOTF;
            const ull* s8 = (const ull*)s4;       // [0:32)=bh pairs, [32:64)=C pairs
            const float x = s4[128 + tid];
            const float dAv = s4[256];
            const ull dAp = f32x2_pack(dAv, dAv);
            const ull cfp = f32x2_pack(x, x);
            ull accA = 0ull, accB = 0ull, accC = 0ull, accD = 0ull;
            #pragma unroll
            for (int j = 0; j < 32; ++j) {
                state[j] = f32x2_fma(dAp, state[j], f32x2_mul(cfp, s8[j]));
                switch (j & 3) {
                    case 0: accA = f32x2_fma(s8[32 + j], state[j], accA); break;
                    case 1: accB = f32x2_fma(s8[32 + j], state[j], accB); break;
                    case 2: accC = f32x2_fma(s8[32 + j], state[j], accC); break;
                    default: accD = f32x2_fma(s8[32 + j], state[j], accD); break;
                }
            }
            float2 a = f32x2_unpack(accA);
            float2 c = f32x2_unpack(accB);
            float2 e = f32x2_unpack(accC);
            float2 f = f32x2_unpack(accD);
            yp[(size_t)(s * SS + i) * DIN] =
                __float2half(((a.x + a.y) + (c.x + c.y)) + ((e.x + e.y) + (f.x + f.y)));
        }
        issue(s + DST - 1);
    }
}

// ---------------- 6) combine partials + D*x + gate + RMSNorm -> split bf16 (vectorized) ----------------
__global__ void combine_kernel(const float* __restrict__ D_param,
                               const float* __restrict__ rms_w) {
    const int row = blockIdx.x, tid = threadIdx.x;
    __shared__ float red[256];
    const int c0 = tid * 4;

    float s0 = 0.f, s1 = 0.f, s2 = 0.f, s3 = 0.f;
    #pragma unroll
    for (int part = 0; part < NPART; ++part) {
        uint2 v = *(const uint2*)(g_ypart + ((size_t)part * ROWS + row) * DIN + c0);
        const __half2* hp = (const __half2*)&v;
        float2 f0 = __half22float2(hp[0]);
        float2 f1 = __half22float2(hp[1]);
        s0 += f0.x; s1 += f0.y; s2 += f1.x; s3 += f1.y;
    }
    const float Dh = D_param[c0 >> 7];
    const float4 xs = *(const float4*)(g_xsh + (size_t)row * PP + (c0 & 127));
    s0 = fmaf(Dh, xs.x, s0); s1 = fmaf(Dh, xs.y, s1);
    s2 = fmaf(Dh, xs.z, s2); s3 = fmaf(Dh, xs.w, s3);

    const float4 z = *(const float4*)(g_zx + (size_t)row * DPROJP + c0);
    float y0 = s0 * siluf(z.x), y1 = s1 * siluf(z.y);
    float y2 = s2 * siluf(z.z), y3 = s3 * siluf(z.w);

    red[tid] = y0 * y0 + y1 * y1 + y2 * y2 + y3 * y3;
    __syncthreads();
    #pragma unroll
    for (int s = 128; s > 0; s >>= 1) { if (tid < s) red[tid] += red[tid + s]; __syncthreads(); }
    const float rstd = rsqrtf(red[0] * (1.f / (float)DIN) + EPS_);

    const float4 rw = *(const float4*)(rms_w + c0);
    float v0 = y0 * rstd * rw.x, v1 = y1 * rstd * rw.y;
    float v2 = y2 * rstd * rw.z, v3 = y3 * rstd * rw.w;

    __nv_bfloat16 hv[4], lv[4];
    split_bf16(v0, hv[0], lv[0]); split_bf16(v1, hv[1], lv[1]);
    split_bf16(v2, hv[2], lv[2]); split_bf16(v3, hv[3], lv[3]);
    *(uint2*)(g_yh + (size_t)row * DIN + c0) = *(const uint2*)hv;
    *(uint2*)(g_yl + (size_t)row * DIN + c0) = *(const uint2*)lv;
}

// ---------------- launch ----------------
extern "C" void kernel_launch(void* const* d_in, const int* in_sizes, int n_in,
                              void* d_out, int out_size) {
    const float* u        = (const float*)d_in[0];
    const float* ln_gamma = (const float*)d_in[1];
    const float* ln_beta  = (const float*)d_in[2];
    const float* W_in     = (const float*)d_in[3];
    const float* conv_w   = (const float*)d_in[4];
    const float* conv_b   = (const float*)d_in[5];
    const float* dt_bias  = (const float*)d_in[6];
    const float* A_log    = (const float*)d_in[7];
    const float* D_param  = (const float*)d_in[8];
    const float* B_scale  = (const float*)d_in[9];
    const float* rms_w    = (const float*)d_in[10];
    const float* W_out    = (const float*)d_in[11];
    float* out = (float*)d_out;

    cudaFuncSetAttribute(mma_gemm_kernel<8>,
                         cudaFuncAttributeMaxDynamicSharedMemorySize, GEMM_SMEM);
    cudaFuncSetAttribute(mma_gemm_kernel<32>,
                         cudaFuncAttributeMaxDynamicSharedMemorySize, GEMM_SMEM);

    __nv_bfloat16 *p_xh, *p_xl, *p_winh, *p_winl, *p_wouth, *p_woutl, *p_yh, *p_yl;
    float* p_zx;
    cudaGetSymbolAddress((void**)&p_xh, g_xh);
    cudaGetSymbolAddress((void**)&p_xl, g_xl);
    cudaGetSymbolAddress((void**)&p_winh, g_WinT_h);
    cudaGetSymbolAddress((void**)&p_winl, g_WinT_l);
    cudaGetSymbolAddress((void**)&p_wouth, g_WoutT_h);
    cudaGetSymbolAddress((void**)&p_woutl, g_WoutT_l);
    cudaGetSymbolAddress((void**)&p_yh, g_yh);
    cudaGetSymbolAddress((void**)&p_yl, g_yl);
    cudaGetSymbolAddress((void**)&p_zx, g_zx);

    ln_kernel<<<ROWS, 256>>>(u, ln_gamma, ln_beta);
    transpose_win_kernel<<<dim3(DPROJP / 32, DM / 32), dim3(32, 8)>>>(W_in);
    transpose_wout_kernel<<<dim3(DM / 32, DIN / 32), dim3(32, 8)>>>(W_out);

    // GEMM1: zx[8192 x 2432(pad)] = xn @ W_in  (split-bf16 HMMA)
    mma_gemm_kernel<8><<<dim3(DPROJP / 128, ROWS / 128), 256, GEMM_SMEM>>>(
        p_xh, p_xl, p_winh, p_winl, p_zx, DPROJP, nullptr);

    conv_kernel<<<dim3(DCONVCH / 256, LL / CLT, BB), 256>>>(conv_w, conv_b);
    prep_kernel<<<ROWS, 128>>>(B_scale, dt_bias, A_log);

    // chunked scan (NPART=2)
    scan_state_kernel<<<dim3(NPART, HH, BB * (NCH - 1)), 128>>>();
    scan_y_kernel<<<dim3(NPART, HH, BB * NCH), 128>>>();

    combine_kernel<<<ROWS, 256>>>(D_param, rms_w);

    // GEMM2: out[8192 x 256] = yg @ W_out + u
    mma_gemm_kernel<32><<<dim3(DM / 128, ROWS / 128), 256, GEMM_SMEM>>>(
        p_yh, p_yl, p_wouth, p_woutl, out, DM, u);
}

// round 15
// speedup vs baseline: 1.0524x; 1.0307x over previous
#include <cuda_runtime.h>
#include <cuda_bf16.h>
#include <cuda_fp16.h>
#include <math.h>
#include <stdint.h>

// ---------------- problem constants ----------------
#define BB 2
#define LL 4096
#define DM 256
#define DIN 1024          // D_INNER
#define GN_ 128           // NGROUPS*D_STATE
#define HH 8              // NHEADS
#define PP 128            // HEADDIM
#define DPROJ 2312        // D_IN_PROJ (logical)
#define DPROJP 2432       // padded to 19*128
#define DCONVCH 1280      // D_INNER + 2*GN
#define ROWS (BB*LL)      // 8192
#define EPS_ 1e-5f

#define NPART 2
#define NPN 64            // n per partition
#define SS 8              // scan superstep (timesteps per pipeline stage)
#define DST 4             // pipeline depth (stages)

// chunked scan
#define NCH 8
#define CLEN (LL / NCH)   // 512
#define NSUPC (CLEN / SS) // 64

// ---------------- scratch (static device allocations) ----------------
__device__ __align__(16) __nv_bfloat16 g_xh[(size_t)ROWS * DM];
__device__ __align__(16) __nv_bfloat16 g_xl[(size_t)ROWS * DM];
__device__ __align__(16) __nv_bfloat16 g_WinT_h[(size_t)DPROJP * DM];
__device__ __align__(16) __nv_bfloat16 g_WinT_l[(size_t)DPROJP * DM];
__device__ __align__(16) __nv_bfloat16 g_WoutT_h[(size_t)DM * DIN];
__device__ __align__(16) __nv_bfloat16 g_WoutT_l[(size_t)DM * DIN];
__device__ __align__(16) __nv_bfloat16 g_yh[(size_t)ROWS * DIN];
__device__ __align__(16) __nv_bfloat16 g_yl[(size_t)ROWS * DIN];
__device__ float g_zx[(size_t)ROWS * DPROJP];
__device__ float g_xconv[(size_t)ROWS * DCONVCH];
__device__ float g_dA[(size_t)ROWS * HH];
__device__ float g_xsh[(size_t)ROWS * PP];
__device__ float g_bh[(size_t)ROWS * HH * GN_];    // B*bscale*dt (33.5 MB)
__device__ __align__(16) __half g_ypart[(size_t)NPART * ROWS * DIN];   // fp16 partials (32 MB)

typedef unsigned long long ull;
// chunk boundary states: lin = ((ch*NPART+part)*HH+h)*BB+b, ch in 0..NCH-2
__device__ __align__(16) ull g_sf[(NCH - 1) * NPART * HH * BB][32][128];   // 7.3 MB
__device__ float g_aprod[(NCH - 1) * NPART * HH * BB];

// ---------------- small helpers ----------------
__device__ __forceinline__ float siluf(float x) { return x / (1.f + expf(-x)); }

__device__ __forceinline__ void split_bf16(float v, __nv_bfloat16& h, __nv_bfloat16& l) {
    h = __float2bfloat16(v);
    l = __float2bfloat16(v - __bfloat162float(h));
}

__device__ __forceinline__ ull f32x2_fma(ull a, ull b, ull c) {
    ull d; asm("fma.rn.f32x2 %0, %1, %2, %3;" : "=l"(d) : "l"(a), "l"(b), "l"(c)); return d;
}
__device__ __forceinline__ ull f32x2_mul(ull a, ull b) {
    ull d; asm("mul.rn.f32x2 %0, %1, %2;" : "=l"(d) : "l"(a), "l"(b)); return d;
}
__device__ __forceinline__ ull f32x2_pack(float lo, float hi) {
    ull d; asm("mov.b64 %0, {%1, %2};" : "=l"(d) : "f"(lo), "f"(hi)); return d;
}
__device__ __forceinline__ float2 f32x2_unpack(ull v) {
    float2 r; asm("mov.b64 {%0, %1}, %2;" : "=f"(r.x), "=f"(r.y) : "l"(v)); return r;
}

__device__ __forceinline__ uint32_t smem_u32(const void* p) {
    uint32_t a;
    asm("{ .reg .u64 t; cvta.to.shared.u64 t, %1; cvt.u32.u64 %0, t; }" : "=r"(a) : "l"(p));
    return a;
}

// ---------------- async copy helpers ----------------
__device__ __forceinline__ void cp_async16(uint32_t saddr, const void* gptr) {
    asm volatile("cp.async.cg.shared.global [%0], [%1], 16;"
                 :: "r"(saddr), "l"(gptr) : "memory");
}
__device__ __forceinline__ void cp_async4(uint32_t saddr, const void* gptr) {
    asm volatile("cp.async.ca.shared.global [%0], [%1], 4;"
                 :: "r"(saddr), "l"(gptr) : "memory");
}
#define CP_COMMIT() asm volatile("cp.async.commit_group;" ::: "memory")
template <int N> __device__ __forceinline__ void cp_wait() {
    asm volatile("cp.async.wait_group %0;" :: "n"(N) : "memory");
}

__device__ __forceinline__ void ldmatrix_x4(uint32_t* r, uint32_t addr) {
    asm volatile("ldmatrix.sync.aligned.m8n8.x4.shared.b16 {%0,%1,%2,%3}, [%4];"
                 : "=r"(r[0]), "=r"(r[1]), "=r"(r[2]), "=r"(r[3]) : "r"(addr));
}

__device__ __forceinline__ void mma_bf16(float* c, const uint32_t* a, uint32_t b0, uint32_t b1) {
    asm volatile(
        "mma.sync.aligned.m16n8k16.row.col.f32.bf16.bf16.f32 "
        "{%0,%1,%2,%3}, {%4,%5,%6,%7}, {%8,%9}, {%0,%1,%2,%3};"
        : "+f"(c[0]), "+f"(c[1]), "+f"(c[2]), "+f"(c[3])
        : "r"(a[0]), "r"(a[1]), "r"(a[2]), "r"(a[3]), "r"(b0), "r"(b1));
}

// ---------------- 1) LayerNorm -> split bf16 (single-pass, shuffle) ----------------
__global__ void ln_kernel(const float* __restrict__ u,
                          const float* __restrict__ gamma,
                          const float* __restrict__ beta) {
    __shared__ float w1[8], w2[8], bc[2];
    const int row = blockIdx.x, tid = threadIdx.x;
    const int wid = tid >> 5, lane = tid & 31;
    float v = u[(size_t)row * DM + tid];
    float s1 = v, s2 = v * v;
    #pragma unroll
    for (int o = 16; o > 0; o >>= 1) {
        s1 += __shfl_xor_sync(0xffffffffu, s1, o);
        s2 += __shfl_xor_sync(0xffffffffu, s2, o);
    }
    if (lane == 0) { w1[wid] = s1; w2[wid] = s2; }
    __syncthreads();
    if (wid == 0) {
        float a = (lane < 8) ? w1[lane] : 0.f;
        float b = (lane < 8) ? w2[lane] : 0.f;
        #pragma unroll
        for (int o = 4; o > 0; o >>= 1) {
            a += __shfl_xor_sync(0xffffffffu, a, o);
            b += __shfl_xor_sync(0xffffffffu, b, o);
        }
        if (lane == 0) {
            float mu = a * (1.f / 256.f);
            float var = b * (1.f / 256.f) - mu * mu;
            bc[0] = mu;
            bc[1] = rsqrtf(var + EPS_);
        }
    }
    __syncthreads();
    float xn = (v - bc[0]) * bc[1] * gamma[tid] + beta[tid];
    __nv_bfloat16 h, l;
    split_bf16(xn, h, l);
    g_xh[(size_t)row * DM + tid] = h;
    g_xl[(size_t)row * DM + tid] = l;
}

// ---------------- transposes + split of weights (tiled, coalesced) ----------------
__global__ void transpose_win_kernel(const float* __restrict__ W_in) {
    __shared__ float tile[32][33];
    const int tx = threadIdx.x, ty = threadIdx.y;        // 32 x 8
    const int n0 = blockIdx.x * 32, k0 = blockIdx.y * 32;
    #pragma unroll
    for (int dy = 0; dy < 32; dy += 8) {
        const int n = n0 + tx, k = k0 + ty + dy;
        tile[ty + dy][tx] = (n < DPROJ) ? W_in[(size_t)k * DPROJ + n] : 0.f;
    }
    __syncthreads();
    #pragma unroll
    for (int dy = 0; dy < 32; dy += 8) {
        const int n = n0 + ty + dy, k = k0 + tx;
        float v = tile[tx][ty + dy];
        __nv_bfloat16 h, l;
        split_bf16(v, h, l);
        g_WinT_h[(size_t)n * DM + k] = h;
        g_WinT_l[(size_t)n * DM + k] = l;
    }
}

__global__ void transpose_wout_kernel(const float* __restrict__ W_out) {
    __shared__ float tile[32][33];
    const int tx = threadIdx.x, ty = threadIdx.y;        // 32 x 8
    const int n0 = blockIdx.x * 32, k0 = blockIdx.y * 32;
    #pragma unroll
    for (int dy = 0; dy < 32; dy += 8) {
        tile[ty + dy][tx] = W_out[(size_t)(k0 + ty + dy) * DM + n0 + tx];
    }
    __syncthreads();
    #pragma unroll
    for (int dy = 0; dy < 32; dy += 8) {
        const int n = n0 + ty + dy, k = k0 + tx;
        float v = tile[tx][ty + dy];
        __nv_bfloat16 h, l;
        split_bf16(v, h, l);
        g_WoutT_h[(size_t)n * DIN + k] = h;
        g_WoutT_l[(size_t)n * DIN + k] = l;
    }
}

// ---------------- 2) split-bf16 GEMM (R9 proven: 3-stage, sequential segments) ----------------
#define GSTR 40  // smem row stride (bf16): 80B rows, 16B-aligned, conflict-free ldmatrix
#define ABUF (128 * GSTR * 2)         // bytes per stage per operand (10240)
#define GEMM_SMEM (6 * ABUF)          // 61440

template <int CPS>
__global__ void __launch_bounds__(256)
mma_gemm_kernel(const __nv_bfloat16* __restrict__ Ah,
                const __nv_bfloat16* __restrict__ Al,
                const __nv_bfloat16* __restrict__ Bh,
                const __nv_bfloat16* __restrict__ Bl,
                float* __restrict__ C, int ldc,
                const float* __restrict__ Cadd) {
    constexpr int Kin = CPS * 32;
    constexpr int T = 3 * CPS;
    extern __shared__ char dsmem[];
    const uint32_t sbase = smem_u32(dsmem);

    const int tid = threadIdx.x;
    const int wid = tid >> 5, lid = tid & 31;
    const int wm = wid >> 2;           // 0..1
    const int wn = wid & 3;            // 0..3
    const int tileRow = blockIdx.y * 128;
    const int tileCol = blockIdx.x * 128;

    const int stRow = tid >> 1;
    const int stSeg = (tid & 1) * 16;
    const uint32_t stOffB = (uint32_t)(stRow * GSTR + stSeg) * 2;

    const int aRowOff = (lid & 7) + ((lid >> 3) & 1) * 8;
    const int aKOff   = (lid >> 4) * 8;
    const int bNOff   = (lid & 7) + ((lid >> 4) & 1) * 8;
    const int bKOff   = ((lid >> 3) & 1) * 8;

    float acc[4][4][4];
    #pragma unroll
    for (int i = 0; i < 4; ++i)
        #pragma unroll
        for (int j = 0; j < 4; ++j)
            #pragma unroll
            for (int q = 0; q < 4; ++q) acc[i][j][q] = 0.f;

    auto issue = [&](int c) {
        if (c < T) {
            const int seg = c / CPS;
            const int kc = c - seg * CPS;
            const __nv_bfloat16* Ag = (seg == 1) ? Al : Ah;
            const __nv_bfloat16* Bg = (seg == 2) ? Bl : Bh;
            const __nv_bfloat16* ga = Ag + (size_t)(tileRow + stRow) * Kin + kc * 32 + stSeg;
            const __nv_bfloat16* gb = Bg + (size_t)(tileCol + stRow) * Kin + kc * 32 + stSeg;
            const int buf = c % 3;
            const uint32_t sa = sbase + (uint32_t)buf * ABUF + stOffB;
            const uint32_t sb = sbase + (uint32_t)(3 + buf) * ABUF + stOffB;
            cp_async16(sa, ga);
            cp_async16(sa + 16, ga + 8);
            cp_async16(sb, gb);
            cp_async16(sb + 16, gb + 8);
        }
        CP_COMMIT();
    };

    issue(0); issue(1);
    for (int c = 0; c < T; ++c) {
        cp_wait<1>();
        __syncthreads();

        const int buf = c % 3;
        const uint32_t aB = sbase + (uint32_t)buf * ABUF;
        const uint32_t bB = sbase + (uint32_t)(3 + buf) * ABUF;

        uint32_t afr[2][4][4];
        uint32_t bfr[2][2][4];
        #pragma unroll
        for (int kk2 = 0; kk2 < 2; ++kk2) {
            const int kk = kk2 * 16;
            #pragma unroll
            for (int mt = 0; mt < 4; ++mt) {
                uint32_t addr = aB + (uint32_t)((wm * 64 + mt * 16 + aRowOff) * GSTR + kk + aKOff) * 2;
                ldmatrix_x4(afr[kk2][mt], addr);
            }
            #pragma unroll
            for (int pr = 0; pr < 2; ++pr) {
                uint32_t addr = bB + (uint32_t)((wn * 32 + pr * 16 + bNOff) * GSTR + kk + bKOff) * 2;
                ldmatrix_x4(bfr[kk2][pr], addr);
            }
        }

        issue(c + 2);

        #pragma unroll
        for (int kk2 = 0; kk2 < 2; ++kk2)
            #pragma unroll
            for (int mt = 0; mt < 4; ++mt)
                #pragma unroll
                for (int nt = 0; nt < 4; ++nt) {
                    const uint32_t* bp = bfr[kk2][nt >> 1];
                    const int hi = (nt & 1) * 2;
                    mma_bf16(acc[mt][nt], afr[kk2][mt], bp[hi], bp[hi + 1]);
                }
    }

    const int gID = lid >> 2, qid = lid & 3;
    #pragma unroll
    for (int mt = 0; mt < 4; ++mt) {
        const int r0 = tileRow + wm * 64 + mt * 16 + gID;
        #pragma unroll
        for (int nt = 0; nt < 4; ++nt) {
            const int col = tileCol + wn * 32 + nt * 8 + qid * 2;
            float2 v0 = make_float2(acc[mt][nt][0], acc[mt][nt][1]);
            float2 v1 = make_float2(acc[mt][nt][2], acc[mt][nt][3]);
            if (Cadd) {
                const float2 a0 = *(const float2*)(Cadd + (size_t)r0 * ldc + col);
                const float2 a1 = *(const float2*)(Cadd + (size_t)(r0 + 8) * ldc + col);
                v0.x += a0.x; v0.y += a0.y;
                v1.x += a1.x; v1.y += a1.y;
            }
            *(float2*)(C + (size_t)r0 * ldc + col) = v0;
            *(float2*)(C + (size_t)(r0 + 8) * ldc + col) = v1;
        }
    }
}

// ---------------- 3) causal depthwise conv (K=4) + SiLU, register ring over l ----------------
#define CLT 16
__global__ void conv_kernel(const float* __restrict__ conv_w,
                            const float* __restrict__ conv_b) {
    const int c = blockIdx.x * 256 + threadIdx.x;   // 0..1279 (grid.x = 5)
    const int l0 = blockIdx.y * CLT;
    const int b = blockIdx.z;
    const size_t base = ((size_t)b * LL) * DPROJP + DIN + c;
    const float w0 = conv_w[c * 4 + 0], w1 = conv_w[c * 4 + 1];
    const float w2 = conv_w[c * 4 + 2], w3 = conv_w[c * 4 + 3];
    const float bias = conv_b[c];

    float x0 = 0.f, x1 = 0.f, x2 = 0.f;
    if (l0 > 0) {
        x0 = g_zx[base + (size_t)(l0 - 3) * DPROJP];
        x1 = g_zx[base + (size_t)(l0 - 2) * DPROJP];
        x2 = g_zx[base + (size_t)(l0 - 1) * DPROJP];
    }
    #pragma unroll
    for (int i = 0; i < CLT; ++i) {
        const float x3 = g_zx[base + (size_t)(l0 + i) * DPROJP];
        float acc = fmaf(x0, w0, bias);
        acc = fmaf(x1, w1, acc);
        acc = fmaf(x2, w2, acc);
        acc = fmaf(x3, w3, acc);
        g_xconv[((size_t)b * LL + l0 + i) * DCONVCH + c] = siluf(acc);
        x0 = x1; x1 = x2; x2 = x3;
    }
}

// ---------------- 4) prep: dt/dA + x_shared mean + prescaled B (fused) ----------------
__global__ void prep_kernel(const float* __restrict__ Bscale,
                            const float* __restrict__ dt_bias,
                            const float* __restrict__ A_log) {
    __shared__ float sdt[HH];
    const int row = blockIdx.x, p = threadIdx.x;    // 128 threads
    if (p < HH) {
        float dt = g_zx[(size_t)row * DPROJP + 2304 + p] + dt_bias[p];
        float dtp = (dt > 20.f) ? dt : log1pf(expf(dt));
        sdt[p] = dtp;
        g_dA[row * HH + p] = expf(-expf(A_log[p]) * dtp);
    }
    const float* xrow = g_xconv + (size_t)row * DCONVCH;
    float s = 0.f;
    #pragma unroll
    for (int h = 0; h < HH; ++h) s += xrow[h * PP + p];
    g_xsh[(size_t)row * PP + p] = s * 0.125f;
    __syncthreads();
    const float Bn = xrow[DIN + p];                  // p == n here
    float* dst = g_bh + (size_t)row * (HH * GN_) + p;
    #pragma unroll
    for (int h = 0; h < HH; ++h)
        dst[h * GN_] = Bn * Bscale[h * GN_ + p] * sdt[h];
}

// ---------------- 5a) chunked scan pass 1: suffix-weighted state (reverse order) ----------------
// state_f[n] = sum_t (prod_{s>t} dA_s) * bh_t[n] * x_t[p]; process t descending with
// running scalar W (1 packed fma per state per timestep instead of fma+mul).
// slot: [0:64) bh, [64:192) xsh, [192] dA, pad to 200
#define SLOT1 200

__global__ void __launch_bounds__(128, 1)
scan_state_kernel() {
    __shared__ __align__(16) float ring[DST][SS][SLOT1];

    const int part = blockIdx.x, h = blockIdx.y;
    const int b = blockIdx.z % BB, ch = blockIdx.z / BB;   // ch in 0..NCH-2
    const int tid = threadIdx.x;                 // = p
    const int n0 = part * NPN;
    const int lane16 = tid & 15;
    const int tgrp = tid >> 4;
    const size_t row0 = (size_t)b * LL + (size_t)ch * CLEN;

    ull acc[32];
    #pragma unroll
    for (int j = 0; j < 32; ++j) acc[j] = 0ull;

    auto issue = [&](int s) {
        if (s >= 0 && s < NSUPC) {
            const size_t row = row0 + (size_t)s * SS + tgrp;
            float* dstT = &ring[s & (DST - 1)][tgrp][0];
            const float* bhrow  = g_bh + (row * HH + h) * GN_ + n0;
            const float* xshrow = g_xsh + row * PP;
            #pragma unroll
            for (int c = lane16; c < 48; c += 16) {
                const float* src;
                float* dst;
                if (c < 16) { src = bhrow + c * 4;         dst = dstT + c * 4; }
                else        { src = xshrow + (c - 16) * 4; dst = dstT + 64 + (c - 16) * 4; }
                cp_async16(smem_u32(dst), src);
            }
            if (lane16 == 8) cp_async4(smem_u32(dstT + 192), g_dA + row * HH + h);
        }
        CP_COMMIT();
    };

    #pragma unroll
    for (int k = 0; k < DST - 1; ++k) issue(NSUPC - 1 - k);

    float W = 1.f;
    for (int s = NSUPC - 1; s >= 0; --s) {
        cp_wait<DST - 2>();
        __syncthreads();

        const float* slotp = &ring[s & (DST - 1)][0][0];
        #pragma unroll
        for (int i = SS - 1; i >= 0; --i) {
            const float* s4 = slotp + i * SLOT1;
            const ull* s8 = (const ull*)s4;       // [0:32) = bh pairs
            const float coef = W * s4[64 + tid];
            W *= s4[192];
            const ull cfp = f32x2_pack(coef, coef);
            #pragma unroll
            for (int j = 0; j < 32; ++j)
                acc[j] = f32x2_fma(cfp, s8[j], acc[j]);
        }
        issue(s - (DST - 1));
    }

    const int lin = ((ch * NPART + part) * HH + h) * BB + b;
    #pragma unroll
    for (int j = 0; j < 32; ++j) g_sf[lin][j][tid] = acc[j];
    if (tid == 0) g_aprod[lin] = W;
}

// ---------------- 5b) chunked scan pass 2: full scan per chunk with combined init ----------------
// slot (264 floats): [0:64) bh, [64:128) C, [128:256) xsh, [256] dA, pad to 264
#define SLOTF 264

__global__ void __launch_bounds__(128, 1)
scan_y_kernel() {
    __shared__ __align__(16) float ring[DST][SS][SLOTF];

    const int part = blockIdx.x, h = blockIdx.y;
    const int b = blockIdx.z % BB, ch = blockIdx.z / BB;   // ch in 0..NCH-1
    const int tid = threadIdx.x;                 // = p
    const int n0 = part * NPN;
    const int lane16 = tid & 15;
    const int tgrp = tid >> 4;
    const size_t row0 = (size_t)b * LL + (size_t)ch * CLEN;

    ull state[32];
    #pragma unroll
    for (int j = 0; j < 32; ++j) state[j] = 0ull;
    if (ch > 0) {
        float w = 1.f;
        for (int k = ch - 1; k >= 0; --k) {
            const int lin = ((k * NPART + part) * HH + h) * BB + b;
            const ull wp = f32x2_pack(w, w);
            #pragma unroll
            for (int j = 0; j < 32; ++j)
                state[j] = f32x2_fma(wp, g_sf[lin][j][tid], state[j]);
            w *= g_aprod[lin];
        }
    }

    auto issue = [&](int s) {
        if (s < NSUPC) {
            const size_t row = row0 + (size_t)s * SS + tgrp;
            float* dstT = &ring[s & (DST - 1)][tgrp][0];
            const float* bhrow   = g_bh + (row * HH + h) * GN_ + n0;
            const float* convrow = g_xconv + row * DCONVCH;
            const float* xshrow  = g_xsh + row * PP;
            #pragma unroll
            for (int c = lane16; c < 64; c += 16) {
                const float* src;
                float* dst;
                if (c < 16)      { src = bhrow + c * 4;                            dst = dstT + c * 4; }
                else if (c < 32) { src = convrow + DIN + GN_ + n0 + (c - 16) * 4;  dst = dstT + 64 + (c - 16) * 4; }
                else             { src = xshrow + (c - 32) * 4;                    dst = dstT + 128 + (c - 32) * 4; }
                cp_async16(smem_u32(dst), src);
            }
            if (lane16 == 8) cp_async4(smem_u32(dstT + 256), g_dA + row * HH + h);
        }
        CP_COMMIT();
    };

    #pragma unroll
    for (int s = 0; s < DST - 1; ++s) issue(s);

    __half* yp = g_ypart + ((size_t)part * ROWS + row0) * DIN + (size_t)h * PP + tid;

    for (int s = 0; s < NSUPC; ++s) {
        cp_wait<DST - 2>();
        __syncthreads();

        const float* slotp = &ring[s & (DST - 1)][0][0];
        #pragma unroll
        for (int i = 0; i < SS; ++i) {
            const float* s4 = slotp + i * SLOTF;
            const ull* s8 = (const ull*)s4;       // [0:32)=bh pairs, [32:64)=C pairs
            const float x = s4[128 + tid];
            const float dAv = s4[256];
            const ull dAp = f32x2_pack(dAv, dAv);
            const ull cfp = f32x2_pack(x, x);
            ull accA = 0ull, accB = 0ull, accC = 0ull, accD = 0ull;
            #pragma unroll
            for (int j = 0; j < 32; ++j) {
                state[j] = f32x2_fma(dAp, state[j], f32x2_mul(cfp, s8[j]));
                switch (j & 3) {
                    case 0: accA = f32x2_fma(s8[32 + j], state[j], accA); break;
                    case 1: accB = f32x2_fma(s8[32 + j], state[j], accB); break;
                    case 2: accC = f32x2_fma(s8[32 + j], state[j], accC); break;
                    default: accD = f32x2_fma(s8[32 + j], state[j], accD); break;
                }
            }
            float2 a = f32x2_unpack(accA);
            float2 c = f32x2_unpack(accB);
            float2 e = f32x2_unpack(accC);
            float2 f = f32x2_unpack(accD);
            yp[(size_t)(s * SS + i) * DIN] =
                __float2half(((a.x + a.y) + (c.x + c.y)) + ((e.x + e.y) + (f.x + f.y)));
        }
        issue(s + DST - 1);
    }
}

// ---------------- 6) combine partials + D*x + gate + RMSNorm -> split bf16 (vectorized) ----------------
__global__ void combine_kernel(const float* __restrict__ D_param,
                               const float* __restrict__ rms_w) {
    const int row = blockIdx.x, tid = threadIdx.x;
    __shared__ float red[256];
    const int c0 = tid * 4;

    float s0 = 0.f, s1 = 0.f, s2 = 0.f, s3 = 0.f;
    #pragma unroll
    for (int part = 0; part < NPART; ++part) {
        uint2 v = *(const uint2*)(g_ypart + ((size_t)part * ROWS + row) * DIN + c0);
        const __half2* hp = (const __half2*)&v;
        float2 f0 = __half22float2(hp[0]);
        float2 f1 = __half22float2(hp[1]);
        s0 += f0.x; s1 += f0.y; s2 += f1.x; s3 += f1.y;
    }
    const float Dh = D_param[c0 >> 7];
    const float4 xs = *(const float4*)(g_xsh + (size_t)row * PP + (c0 & 127));
    s0 = fmaf(Dh, xs.x, s0); s1 = fmaf(Dh, xs.y, s1);
    s2 = fmaf(Dh, xs.z, s2); s3 = fmaf(Dh, xs.w, s3);

    const float4 z = *(const float4*)(g_zx + (size_t)row * DPROJP + c0);
    float y0 = s0 * siluf(z.x), y1 = s1 * siluf(z.y);
    float y2 = s2 * siluf(z.z), y3 = s3 * siluf(z.w);

    red[tid] = y0 * y0 + y1 * y1 + y2 * y2 + y3 * y3;
    __syncthreads();
    #pragma unroll
    for (int s = 128; s > 0; s >>= 1) { if (tid < s) red[tid] += red[tid + s]; __syncthreads(); }
    const float rstd = rsqrtf(red[0] * (1.f / (float)DIN) + EPS_);

    const float4 rw = *(const float4*)(rms_w + c0);
    float v0 = y0 * rstd * rw.x, v1 = y1 * rstd * rw.y;
    float v2 = y2 * rstd * rw.z, v3 = y3 * rstd * rw.w;

    __nv_bfloat16 hv[4], lv[4];
    split_bf16(v0, hv[0], lv[0]); split_bf16(v1, hv[1], lv[1]);
    split_bf16(v2, hv[2], lv[2]); split_bf16(v3, hv[3], lv[3]);
    *(uint2*)(g_yh + (size_t)row * DIN + c0) = *(const uint2*)hv;
    *(uint2*)(g_yl + (size_t)row * DIN + c0) = *(const uint2*)lv;
}

// ---------------- launch ----------------
extern "C" void kernel_launch(void* const* d_in, const int* in_sizes, int n_in,
                              void* d_out, int out_size) {
    const float* u        = (const float*)d_in[0];
    const float* ln_gamma = (const float*)d_in[1];
    const float* ln_beta  = (const float*)d_in[2];
    const float* W_in     = (const float*)d_in[3];
    const float* conv_w   = (const float*)d_in[4];
    const float* conv_b   = (const float*)d_in[5];
    const float* dt_bias  = (const float*)d_in[6];
    const float* A_log    = (const float*)d_in[7];
    const float* D_param  = (const float*)d_in[8];
    const float* B_scale  = (const float*)d_in[9];
    const float* rms_w    = (const float*)d_in[10];
    const float* W_out    = (const float*)d_in[11];
    float* out = (float*)d_out;

    cudaFuncSetAttribute(mma_gemm_kernel<8>,
                         cudaFuncAttributeMaxDynamicSharedMemorySize, GEMM_SMEM);
    cudaFuncSetAttribute(mma_gemm_kernel<32>,
                         cudaFuncAttributeMaxDynamicSharedMemorySize, GEMM_SMEM);

    __nv_bfloat16 *p_xh, *p_xl, *p_winh, *p_winl, *p_wouth, *p_woutl, *p_yh, *p_yl;
    float* p_zx;
    cudaGetSymbolAddress((void**)&p_xh, g_xh);
    cudaGetSymbolAddress((void**)&p_xl, g_xl);
    cudaGetSymbolAddress((void**)&p_winh, g_WinT_h);
    cudaGetSymbolAddress((void**)&p_winl, g_WinT_l);
    cudaGetSymbolAddress((void**)&p_wouth, g_WoutT_h);
    cudaGetSymbolAddress((void**)&p_woutl, g_WoutT_l);
    cudaGetSymbolAddress((void**)&p_yh, g_yh);
    cudaGetSymbolAddress((void**)&p_yl, g_yl);
    cudaGetSymbolAddress((void**)&p_zx, g_zx);

    ln_kernel<<<ROWS, 256>>>(u, ln_gamma, ln_beta);
    transpose_win_kernel<<<dim3(DPROJP / 32, DM / 32), dim3(32, 8)>>>(W_in);
    transpose_wout_kernel<<<dim3(DM / 32, DIN / 32), dim3(32, 8)>>>(W_out);

    // GEMM1: zx[8192 x 2432(pad)] = xn @ W_in  (split-bf16 HMMA, 3-stage sequential)
    mma_gemm_kernel<8><<<dim3(DPROJP / 128, ROWS / 128), 256, GEMM_SMEM>>>(
        p_xh, p_xl, p_winh, p_winl, p_zx, DPROJP, nullptr);

    conv_kernel<<<dim3(DCONVCH / 256, LL / CLT, BB), 256>>>(conv_w, conv_b);
    prep_kernel<<<ROWS, 128>>>(B_scale, dt_bias, A_log);

    // chunked scan (NPART=2): reverse suffix-weight pass 1, forward pass 2
    scan_state_kernel<<<dim3(NPART, HH, BB * (NCH - 1)), 128>>>();
    scan_y_kernel<<<dim3(NPART, HH, BB * NCH), 128>>>();

    combine_kernel<<<ROWS, 256>>>(D_param, rms_w);

    // GEMM2: out[8192 x 256] = yg @ W_out + u
    mma_gemm_kernel<32><<<dim3(DM / 128, ROWS / 128), 256, GEMM_SMEM>>>(
        p_yh, p_yl, p_wouth, p_woutl, out, DM, u);
}

// round 16
// speedup vs baseline: 1.1940x; 1.1346x over previous
#include <cuda_runtime.h>
#include <cuda_bf16.h>
#include <cuda_fp16.h>
#include <math.h>
#include <stdint.h>

// ---------------- problem constants ----------------
#define BB 2
#define LL 4096
#define DM 256
#define DIN 1024          // D_INNER
#define GN_ 128           // NGROUPS*D_STATE
#define HH 8              // NHEADS
#define PP 128            // HEADDIM
#define DPROJ 2312        // D_IN_PROJ (logical)
#define DPROJP 2432       // padded to 19*128
#define DCONVCH 1280      // D_INNER + 2*GN
#define ROWS (BB*LL)      // 8192
#define EPS_ 1e-5f

#define NPART 2
#define NPN 64            // n per partition
#define SS 8              // scan superstep (timesteps per pipeline stage)
#define DST 4             // pipeline depth (stages)

// chunked scan
#define NCH 8
#define CLEN (LL / NCH)   // 512
#define NSUPC (CLEN / SS) // 64

// ---------------- scratch (static device allocations) ----------------
__device__ __align__(16) __half g_xh[(size_t)ROWS * DM];
__device__ __align__(16) __half g_xl[(size_t)ROWS * DM];
__device__ __align__(16) __half g_WinT[(size_t)DPROJP * DM];
__device__ __align__(16) __half g_WoutT[(size_t)DM * DIN];
__device__ __align__(16) __half g_yh[(size_t)ROWS * DIN];
__device__ __align__(16) __half g_yl[(size_t)ROWS * DIN];
__device__ float g_zx[(size_t)ROWS * DPROJP];
__device__ float g_xconv[(size_t)ROWS * DCONVCH];
__device__ float g_dA[(size_t)ROWS * HH];
__device__ float g_xsh[(size_t)ROWS * PP];
__device__ float g_bh[(size_t)ROWS * HH * GN_];    // B*bscale*dt (33.5 MB)
__device__ __align__(16) __half g_ypart[(size_t)NPART * ROWS * DIN];   // fp16 partials (32 MB)

typedef unsigned long long ull;
// chunk boundary states: lin = ((ch*NPART+part)*HH+h)*BB+b, ch in 0..NCH-2
__device__ __align__(16) ull g_sf[(NCH - 1) * NPART * HH * BB][32][128];   // 7.3 MB
__device__ float g_aprod[(NCH - 1) * NPART * HH * BB];

// ---------------- small helpers ----------------
__device__ __forceinline__ float siluf(float x) { return x / (1.f + expf(-x)); }

__device__ __forceinline__ void split_f16(float v, __half& h, __half& l) {
    h = __float2half(v);
    l = __float2half(v - __half2float(h));
}

__device__ __forceinline__ ull f32x2_fma(ull a, ull b, ull c) {
    ull d; asm("fma.rn.f32x2 %0, %1, %2, %3;" : "=l"(d) : "l"(a), "l"(b), "l"(c)); return d;
}
__device__ __forceinline__ ull f32x2_mul(ull a, ull b) {
    ull d; asm("mul.rn.f32x2 %0, %1, %2;" : "=l"(d) : "l"(a), "l"(b)); return d;
}
__device__ __forceinline__ ull f32x2_pack(float lo, float hi) {
    ull d; asm("mov.b64 %0, {%1, %2};" : "=l"(d) : "f"(lo), "f"(hi)); return d;
}
__device__ __forceinline__ float2 f32x2_unpack(ull v) {
    float2 r; asm("mov.b64 {%0, %1}, %2;" : "=f"(r.x), "=f"(r.y) : "l"(v)); return r;
}

__device__ __forceinline__ uint32_t smem_u32(const void* p) {
    uint32_t a;
    asm("{ .reg .u64 t; cvta.to.shared.u64 t, %1; cvt.u32.u64 %0, t; }" : "=r"(a) : "l"(p));
    return a;
}

// ---------------- async copy helpers ----------------
__device__ __forceinline__ void cp_async16(uint32_t saddr, const void* gptr) {
    asm volatile("cp.async.cg.shared.global [%0], [%1], 16;"
                 :: "r"(saddr), "l"(gptr) : "memory");
}
__device__ __forceinline__ void cp_async4(uint32_t saddr, const void* gptr) {
    asm volatile("cp.async.ca.shared.global [%0], [%1], 4;"
                 :: "r"(saddr), "l"(gptr) : "memory");
}
#define CP_COMMIT() asm volatile("cp.async.commit_group;" ::: "memory")
template <int N> __device__ __forceinline__ void cp_wait() {
    asm volatile("cp.async.wait_group %0;" :: "n"(N) : "memory");
}

__device__ __forceinline__ void ldmatrix_x4(uint32_t* r, uint32_t addr) {
    asm volatile("ldmatrix.sync.aligned.m8n8.x4.shared.b16 {%0,%1,%2,%3}, [%4];"
                 : "=r"(r[0]), "=r"(r[1]), "=r"(r[2]), "=r"(r[3]) : "r"(addr));
}

__device__ __forceinline__ void mma_f16(float* c, const uint32_t* a, uint32_t b0, uint32_t b1) {
    asm volatile(
        "mma.sync.aligned.m16n8k16.row.col.f32.f16.f16.f32 "
        "{%0,%1,%2,%3}, {%4,%5,%6,%7}, {%8,%9}, {%0,%1,%2,%3};"
        : "+f"(c[0]), "+f"(c[1]), "+f"(c[2]), "+f"(c[3])
        : "r"(a[0]), "r"(a[1]), "r"(a[2]), "r"(a[3]), "r"(b0), "r"(b1));
}

// ---------------- 1) LayerNorm -> split fp16 (single-pass, shuffle) ----------------
__global__ void ln_kernel(const float* __restrict__ u,
                          const float* __restrict__ gamma,
                          const float* __restrict__ beta) {
    __shared__ float w1[8], w2[8], bc[2];
    const int row = blockIdx.x, tid = threadIdx.x;
    const int wid = tid >> 5, lane = tid & 31;
    float v = u[(size_t)row * DM + tid];
    float s1 = v, s2 = v * v;
    #pragma unroll
    for (int o = 16; o > 0; o >>= 1) {
        s1 += __shfl_xor_sync(0xffffffffu, s1, o);
        s2 += __shfl_xor_sync(0xffffffffu, s2, o);
    }
    if (lane == 0) { w1[wid] = s1; w2[wid] = s2; }
    __syncthreads();
    if (wid == 0) {
        float a = (lane < 8) ? w1[lane] : 0.f;
        float b = (lane < 8) ? w2[lane] : 0.f;
        #pragma unroll
        for (int o = 4; o > 0; o >>= 1) {
            a += __shfl_xor_sync(0xffffffffu, a, o);
            b += __shfl_xor_sync(0xffffffffu, b, o);
        }
        if (lane == 0) {
            float mu = a * (1.f / 256.f);
            float var = b * (1.f / 256.f) - mu * mu;
            bc[0] = mu;
            bc[1] = rsqrtf(var + EPS_);
        }
    }
    __syncthreads();
    float xn = (v - bc[0]) * bc[1] * gamma[tid] + beta[tid];
    __half h, l;
    split_f16(xn, h, l);
    g_xh[(size_t)row * DM + tid] = h;
    g_xl[(size_t)row * DM + tid] = l;
}

// ---------------- transposes of weights (tiled, coalesced, single fp16) ----------------
__global__ void transpose_win_kernel(const float* __restrict__ W_in) {
    __shared__ float tile[32][33];
    const int tx = threadIdx.x, ty = threadIdx.y;        // 32 x 8
    const int n0 = blockIdx.x * 32, k0 = blockIdx.y * 32;
    #pragma unroll
    for (int dy = 0; dy < 32; dy += 8) {
        const int n = n0 + tx, k = k0 + ty + dy;
        tile[ty + dy][tx] = (n < DPROJ) ? W_in[(size_t)k * DPROJ + n] : 0.f;
    }
    __syncthreads();
    #pragma unroll
    for (int dy = 0; dy < 32; dy += 8) {
        const int n = n0 + ty + dy, k = k0 + tx;
        g_WinT[(size_t)n * DM + k] = __float2half(tile[tx][ty + dy]);
    }
}

__global__ void transpose_wout_kernel(const float* __restrict__ W_out) {
    __shared__ float tile[32][33];
    const int tx = threadIdx.x, ty = threadIdx.y;        // 32 x 8
    const int n0 = blockIdx.x * 32, k0 = blockIdx.y * 32;
    #pragma unroll
    for (int dy = 0; dy < 32; dy += 8) {
        tile[ty + dy][tx] = W_out[(size_t)(k0 + ty + dy) * DM + n0 + tx];
    }
    __syncthreads();
    #pragma unroll
    for (int dy = 0; dy < 32; dy += 8) {
        const int n = n0 + ty + dy, k = k0 + tx;
        g_WoutT[(size_t)n * DIN + k] = __float2half(tile[tx][ty + dy]);
    }
}

// ---------------- 2) split-fp16 GEMM: (Ah+Al) @ B^T, 2 K-segments, 3-stage ----------------
#define GSTR 40  // smem row stride (fp16): 80B rows, 16B-aligned, conflict-free ldmatrix
#define ABUF (128 * GSTR * 2)         // bytes per stage per operand (10240)
#define GEMM_SMEM (6 * ABUF)          // 61440

template <int CPS>
__global__ void __launch_bounds__(256)
mma_gemm_kernel(const __half* __restrict__ Ah,
                const __half* __restrict__ Al,
                const __half* __restrict__ B,
                float* __restrict__ C, int ldc,
                const float* __restrict__ Cadd) {
    constexpr int Kin = CPS * 32;
    constexpr int T = 2 * CPS;
    extern __shared__ char dsmem[];
    const uint32_t sbase = smem_u32(dsmem);

    const int tid = threadIdx.x;
    const int wid = tid >> 5, lid = tid & 31;
    const int wm = wid >> 2;           // 0..1
    const int wn = wid & 3;            // 0..3
    const int tileRow = blockIdx.y * 128;
    const int tileCol = blockIdx.x * 128;

    const int stRow = tid >> 1;
    const int stSeg = (tid & 1) * 16;
    const uint32_t stOffB = (uint32_t)(stRow * GSTR + stSeg) * 2;

    const int aRowOff = (lid & 7) + ((lid >> 3) & 1) * 8;
    const int aKOff   = (lid >> 4) * 8;
    const int bNOff   = (lid & 7) + ((lid >> 4) & 1) * 8;
    const int bKOff   = ((lid >> 3) & 1) * 8;

    float acc[4][4][4];
    #pragma unroll
    for (int i = 0; i < 4; ++i)
        #pragma unroll
        for (int j = 0; j < 4; ++j)
            #pragma unroll
            for (int q = 0; q < 4; ++q) acc[i][j][q] = 0.f;

    auto issue = [&](int c) {
        if (c < T) {
            const int seg = c / CPS;
            const int kc = c - seg * CPS;
            const __half* Ag = seg ? Al : Ah;
            const __half* ga = Ag + (size_t)(tileRow + stRow) * Kin + kc * 32 + stSeg;
            const __half* gb = B + (size_t)(tileCol + stRow) * Kin + kc * 32 + stSeg;
            const int buf = c % 3;
            const uint32_t sa = sbase + (uint32_t)buf * ABUF + stOffB;
            const uint32_t sb = sbase + (uint32_t)(3 + buf) * ABUF + stOffB;
            cp_async16(sa, ga);
            cp_async16(sa + 16, ga + 8);
            cp_async16(sb, gb);
            cp_async16(sb + 16, gb + 8);
        }
        CP_COMMIT();
    };

    issue(0); issue(1);
    for (int c = 0; c < T; ++c) {
        cp_wait<1>();
        __syncthreads();

        const int buf = c % 3;
        const uint32_t aB = sbase + (uint32_t)buf * ABUF;
        const uint32_t bB = sbase + (uint32_t)(3 + buf) * ABUF;

        uint32_t afr[2][4][4];
        uint32_t bfr[2][2][4];
        #pragma unroll
        for (int kk2 = 0; kk2 < 2; ++kk2) {
            const int kk = kk2 * 16;
            #pragma unroll
            for (int mt = 0; mt < 4; ++mt) {
                uint32_t addr = aB + (uint32_t)((wm * 64 + mt * 16 + aRowOff) * GSTR + kk + aKOff) * 2;
                ldmatrix_x4(afr[kk2][mt], addr);
            }
            #pragma unroll
            for (int pr = 0; pr < 2; ++pr) {
                uint32_t addr = bB + (uint32_t)((wn * 32 + pr * 16 + bNOff) * GSTR + kk + bKOff) * 2;
                ldmatrix_x4(bfr[kk2][pr], addr);
            }
        }

        issue(c + 2);

        #pragma unroll
        for (int kk2 = 0; kk2 < 2; ++kk2)
            #pragma unroll
            for (int mt = 0; mt < 4; ++mt)
                #pragma unroll
                for (int nt = 0; nt < 4; ++nt) {
                    const uint32_t* bp = bfr[kk2][nt >> 1];
                    const int hi = (nt & 1) * 2;
                    mma_f16(acc[mt][nt], afr[kk2][mt], bp[hi], bp[hi + 1]);
                }
    }

    const int gID = lid >> 2, qid = lid & 3;
    #pragma unroll
    for (int mt = 0; mt < 4; ++mt) {
        const int r0 = tileRow + wm * 64 + mt * 16 + gID;
        #pragma unroll
        for (int nt = 0; nt < 4; ++nt) {
            const int col = tileCol + wn * 32 + nt * 8 + qid * 2;
            float2 v0 = make_float2(acc[mt][nt][0], acc[mt][nt][1]);
            float2 v1 = make_float2(acc[mt][nt][2], acc[mt][nt][3]);
            if (Cadd) {
                const float2 a0 = *(const float2*)(Cadd + (size_t)r0 * ldc + col);
                const float2 a1 = *(const float2*)(Cadd + (size_t)(r0 + 8) * ldc + col);
                v0.x += a0.x; v0.y += a0.y;
                v1.x += a1.x; v1.y += a1.y;
            }
            *(float2*)(C + (size_t)r0 * ldc + col) = v0;
            *(float2*)(C + (size_t)(r0 + 8) * ldc + col) = v1;
        }
    }
}

// ---------------- 3) causal depthwise conv (K=4) + SiLU, register ring over l ----------------
#define CLT 16
__global__ void conv_kernel(const float* __restrict__ conv_w,
                            const float* __restrict__ conv_b) {
    const int c = blockIdx.x * 256 + threadIdx.x;   // 0..1279 (grid.x = 5)
    const int l0 = blockIdx.y * CLT;
    const int b = blockIdx.z;
    const size_t base = ((size_t)b * LL) * DPROJP + DIN + c;
    const float w0 = conv_w[c * 4 + 0], w1 = conv_w[c * 4 + 1];
    const float w2 = conv_w[c * 4 + 2], w3 = conv_w[c * 4 + 3];
    const float bias = conv_b[c];

    float x0 = 0.f, x1 = 0.f, x2 = 0.f;
    if (l0 > 0) {
        x0 = g_zx[base + (size_t)(l0 - 3) * DPROJP];
        x1 = g_zx[base + (size_t)(l0 - 2) * DPROJP];
        x2 = g_zx[base + (size_t)(l0 - 1) * DPROJP];
    }
    #pragma unroll
    for (int i = 0; i < CLT; ++i) {
        const float x3 = g_zx[base + (size_t)(l0 + i) * DPROJP];
        float acc = fmaf(x0, w0, bias);
        acc = fmaf(x1, w1, acc);
        acc = fmaf(x2, w2, acc);
        acc = fmaf(x3, w3, acc);
        g_xconv[((size_t)b * LL + l0 + i) * DCONVCH + c] = siluf(acc);
        x0 = x1; x1 = x2; x2 = x3;
    }
}

// ---------------- 4) prep: dt/dA + x_shared mean + prescaled B (fused) ----------------
__global__ void prep_kernel(const float* __restrict__ Bscale,
                            const float* __restrict__ dt_bias,
                            const float* __restrict__ A_log) {
    __shared__ float sdt[HH];
    const int row = blockIdx.x, p = threadIdx.x;    // 128 threads
    if (p < HH) {
        float dt = g_zx[(size_t)row * DPROJP + 2304 + p] + dt_bias[p];
        float dtp = (dt > 20.f) ? dt : log1pf(expf(dt));
        sdt[p] = dtp;
        g_dA[row * HH + p] = expf(-expf(A_log[p]) * dtp);
    }
    const float* xrow = g_xconv + (size_t)row * DCONVCH;
    float s = 0.f;
    #pragma unroll
    for (int h = 0; h < HH; ++h) s += xrow[h * PP + p];
    g_xsh[(size_t)row * PP + p] = s * 0.125f;
    __syncthreads();
    const float Bn = xrow[DIN + p];                  // p == n here
    float* dst = g_bh + (size_t)row * (HH * GN_) + p;
    #pragma unroll
    for (int h = 0; h < HH; ++h)
        dst[h * GN_] = Bn * Bscale[h * GN_ + p] * sdt[h];
}

// ---------------- 5a) chunked scan pass 1: suffix-weighted state (reverse order) ----------------
// slot: [0:64) bh, [64:192) xsh, [192] dA, pad to 200
#define SLOT1 200

__global__ void __launch_bounds__(128, 1)
scan_state_kernel() {
    __shared__ __align__(16) float ring[DST][SS][SLOT1];

    const int part = blockIdx.x, h = blockIdx.y;
    const int b = blockIdx.z % BB, ch = blockIdx.z / BB;   // ch in 0..NCH-2
    const int tid = threadIdx.x;                 // = p
    const int n0 = part * NPN;
    const int lane16 = tid & 15;
    const int tgrp = tid >> 4;
    const size_t row0 = (size_t)b * LL + (size_t)ch * CLEN;

    ull acc[32];
    #pragma unroll
    for (int j = 0; j < 32; ++j) acc[j] = 0ull;

    auto issue = [&](int s) {
        if (s >= 0 && s < NSUPC) {
            const size_t row = row0 + (size_t)s * SS + tgrp;
            float* dstT = &ring[s & (DST - 1)][tgrp][0];
            const float* bhrow  = g_bh + (row * HH + h) * GN_ + n0;
            const float* xshrow = g_xsh + row * PP;
            #pragma unroll
            for (int c = lane16; c < 48; c += 16) {
                const float* src;
                float* dst;
                if (c < 16) { src = bhrow + c * 4;         dst = dstT + c * 4; }
                else        { src = xshrow + (c - 16) * 4; dst = dstT + 64 + (c - 16) * 4; }
                cp_async16(smem_u32(dst), src);
            }
            if (lane16 == 8) cp_async4(smem_u32(dstT + 192), g_dA + row * HH + h);
        }
        CP_COMMIT();
    };

    #pragma unroll
    for (int k = 0; k < DST - 1; ++k) issue(NSUPC - 1 - k);

    float W = 1.f;
    for (int s = NSUPC - 1; s >= 0; --s) {
        cp_wait<DST - 2>();
        __syncthreads();

        const float* slotp = &ring[s & (DST - 1)][0][0];
        #pragma unroll
        for (int i = SS - 1; i >= 0; --i) {
            const float* s4 = slotp + i * SLOT1;
            const ull* s8 = (const ull*)s4;       // [0:32) = bh pairs
            const float coef = W * s4[64 + tid];
            W *= s4[192];
            const ull cfp = f32x2_pack(coef, coef);
            #pragma unroll
            for (int j = 0; j < 32; ++j)
                acc[j] = f32x2_fma(cfp, s8[j], acc[j]);
        }
        issue(s - (DST - 1));
    }

    const int lin = ((ch * NPART + part) * HH + h) * BB + b;
    #pragma unroll
    for (int j = 0; j < 32; ++j) g_sf[lin][j][tid] = acc[j];
    if (tid == 0) g_aprod[lin] = W;
}

// ---------------- 5b) chunked scan pass 2: full scan per chunk with combined init ----------------
// slot (264 floats): [0:64) bh, [64:128) C, [128:256) xsh, [256] dA, pad to 264
#define SLOTF 264

__global__ void __launch_bounds__(128, 1)
scan_y_kernel() {
    __shared__ __align__(16) float ring[DST][SS][SLOTF];

    const int part = blockIdx.x, h = blockIdx.y;
    const int b = blockIdx.z % BB, ch = blockIdx.z / BB;   // ch in 0..NCH-1
    const int tid = threadIdx.x;                 // = p
    const int n0 = part * NPN;
    const int lane16 = tid & 15;
    const int tgrp = tid >> 4;
    const size_t row0 = (size_t)b * LL + (size_t)ch * CLEN;

    ull state[32];
    #pragma unroll
    for (int j = 0; j < 32; ++j) state[j] = 0ull;
    if (ch > 0) {
        float w = 1.f;
        for (int k = ch - 1; k >= 0; --k) {
            const int lin = ((k * NPART + part) * HH + h) * BB + b;
            const ull wp = f32x2_pack(w, w);
            #pragma unroll
            for (int j = 0; j < 32; ++j)
                state[j] = f32x2_fma(wp, g_sf[lin][j][tid], state[j]);
            w *= g_aprod[lin];
        }
    }

    auto issue = [&](int s) {
        if (s < NSUPC) {
            const size_t row = row0 + (size_t)s * SS + tgrp;
            float* dstT = &ring[s & (DST - 1)][tgrp][0];
            const float* bhrow   = g_bh + (row * HH + h) * GN_ + n0;
            const float* convrow = g_xconv + row * DCONVCH;
            const float* xshrow  = g_xsh + row * PP;
            #pragma unroll
            for (int c = lane16; c < 64; c += 16) {
                const float* src;
                float* dst;
                if (c < 16)      { src = bhrow + c * 4;                            dst = dstT + c * 4; }
                else if (c < 32) { src = convrow + DIN + GN_ + n0 + (c - 16) * 4;  dst = dstT + 64 + (c - 16) * 4; }
                else             { src = xshrow + (c - 32) * 4;                    dst = dstT + 128 + (c - 32) * 4; }
                cp_async16(smem_u32(dst), src);
            }
            if (lane16 == 8) cp_async4(smem_u32(dstT + 256), g_dA + row * HH + h);
        }
        CP_COMMIT();
    };

    #pragma unroll
    for (int s = 0; s < DST - 1; ++s) issue(s);

    __half* yp = g_ypart + ((size_t)part * ROWS + row0) * DIN + (size_t)h * PP + tid;

    for (int s = 0; s < NSUPC; ++s) {
        cp_wait<DST - 2>();
        __syncthreads();

        const float* slotp = &ring[s & (DST - 1)][0][0];
        #pragma unroll
        for (int i = 0; i < SS; ++i) {
            const float* s4 = slotp + i * SLOTF;
            const ull* s8 = (const ull*)s4;       // [0:32)=bh pairs, [32:64)=C pairs
            const float x = s4[128 + tid];
            const float dAv = s4[256];
            const ull dAp = f32x2_pack(dAv, dAv);
            const ull cfp = f32x2_pack(x, x);
            ull accA = 0ull, accB = 0ull, accC = 0ull, accD = 0ull;
            #pragma unroll
            for (int j = 0; j < 32; ++j) {
                state[j] = f32x2_fma(dAp, state[j], f32x2_mul(cfp, s8[j]));
                switch (j & 3) {
                    case 0: accA = f32x2_fma(s8[32 + j], state[j], accA); break;
                    case 1: accB = f32x2_fma(s8[32 + j], state[j], accB); break;
                    case 2: accC = f32x2_fma(s8[32 + j], state[j], accC); break;
                    default: accD = f32x2_fma(s8[32 + j], state[j], accD); break;
                }
            }
            float2 a = f32x2_unpack(accA);
            float2 c = f32x2_unpack(accB);
            float2 e = f32x2_unpack(accC);
            float2 f = f32x2_unpack(accD);
            yp[(size_t)(s * SS + i) * DIN] =
                __float2half(((a.x + a.y) + (c.x + c.y)) + ((e.x + e.y) + (f.x + f.y)));
        }
        issue(s + DST - 1);
    }
}

// ---------------- 6) combine partials + D*x + gate + RMSNorm -> split fp16 (vectorized) ----------------
__global__ void combine_kernel(const float* __restrict__ D_param,
                               const float* __restrict__ rms_w) {
    const int row = blockIdx.x, tid = threadIdx.x;
    __shared__ float red[256];
    const int c0 = tid * 4;

    float s0 = 0.f, s1 = 0.f, s2 = 0.f, s3 = 0.f;
    #pragma unroll
    for (int part = 0; part < NPART; ++part) {
        uint2 v = *(const uint2*)(g_ypart + ((size_t)part * ROWS + row) * DIN + c0);
        const __half2* hp = (const __half2*)&v;
        float2 f0 = __half22float2(hp[0]);
        float2 f1 = __half22float2(hp[1]);
        s0 += f0.x; s1 += f0.y; s2 += f1.x; s3 += f1.y;
    }
    const float Dh = D_param[c0 >> 7];
    const float4 xs = *(const float4*)(g_xsh + (size_t)row * PP + (c0 & 127));
    s0 = fmaf(Dh, xs.x, s0); s1 = fmaf(Dh, xs.y, s1);
    s2 = fmaf(Dh, xs.z, s2); s3 = fmaf(Dh, xs.w, s3);

    const float4 z = *(const float4*)(g_zx + (size_t)row * DPROJP + c0);
    float y0 = s0 * siluf(z.x), y1 = s1 * siluf(z.y);
    float y2 = s2 * siluf(z.z), y3 = s3 * siluf(z.w);

    red[tid] = y0 * y0 + y1 * y1 + y2 * y2 + y3 * y3;
    __syncthreads();
    #pragma unroll
    for (int s = 128; s > 0; s >>= 1) { if (tid < s) red[tid] += red[tid + s]; __syncthreads(); }
    const float rstd = rsqrtf(red[0] * (1.f / (float)DIN) + EPS_);

    const float4 rw = *(const float4*)(rms_w + c0);
    float v0 = y0 * rstd * rw.x, v1 = y1 * rstd * rw.y;
    float v2 = y2 * rstd * rw.z, v3 = y3 * rstd * rw.w;

    __half hv[4], lv[4];
    split_f16(v0, hv[0], lv[0]); split_f16(v1, hv[1], lv[1]);
    split_f16(v2, hv[2], lv[2]); split_f16(v3, hv[3], lv[3]);
    *(uint2*)(g_yh + (size_t)row * DIN + c0) = *(const uint2*)hv;
    *(uint2*)(g_yl + (size_t)row * DIN + c0) = *(const uint2*)lv;
}

// ---------------- launch ----------------
extern "C" void kernel_launch(void* const* d_in, const int* in_sizes, int n_in,
                              void* d_out, int out_size) {
    const float* u        = (const float*)d_in[0];
    const float* ln_gamma = (const float*)d_in[1];
    const float* ln_beta  = (const float*)d_in[2];
    const float* W_in     = (const float*)d_in[3];
    const float* conv_w   = (const float*)d_in[4];
    const float* conv_b   = (const float*)d_in[5];
    const float* dt_bias  = (const float*)d_in[6];
    const float* A_log    = (const float*)d_in[7];
    const float* D_param  = (const float*)d_in[8];
    const float* B_scale  = (const float*)d_in[9];
    const float* rms_w    = (const float*)d_in[10];
    const float* W_out    = (const float*)d_in[11];
    float* out = (float*)d_out;

    cudaFuncSetAttribute(mma_gemm_kernel<8>,
                         cudaFuncAttributeMaxDynamicSharedMemorySize, GEMM_SMEM);
    cudaFuncSetAttribute(mma_gemm_kernel<32>,
                         cudaFuncAttributeMaxDynamicSharedMemorySize, GEMM_SMEM);

    __half *p_xh, *p_xl, *p_win, *p_wout, *p_yh, *p_yl;
    float* p_zx;
    cudaGetSymbolAddress((void**)&p_xh, g_xh);
    cudaGetSymbolAddress((void**)&p_xl, g_xl);
    cudaGetSymbolAddress((void**)&p_win, g_WinT);
    cudaGetSymbolAddress((void**)&p_wout, g_WoutT);
    cudaGetSymbolAddress((void**)&p_yh, g_yh);
    cudaGetSymbolAddress((void**)&p_yl, g_yl);
    cudaGetSymbolAddress((void**)&p_zx, g_zx);

    ln_kernel<<<ROWS, 256>>>(u, ln_gamma, ln_beta);
    transpose_win_kernel<<<dim3(DPROJP / 32, DM / 32), dim3(32, 8)>>>(W_in);
    transpose_wout_kernel<<<dim3(DM / 32, DIN / 32), dim3(32, 8)>>>(W_out);

    // GEMM1: zx[8192 x 2432(pad)] = xn @ W_in  (split-fp16, 2 segments)
    mma_gemm_kernel<8><<<dim3(DPROJP / 128, ROWS / 128), 256, GEMM_SMEM>>>(
        p_xh, p_xl, p_win, p_zx, DPROJP, nullptr);

    conv_kernel<<<dim3(DCONVCH / 256, LL / CLT, BB), 256>>>(conv_w, conv_b);
    prep_kernel<<<ROWS, 128>>>(B_scale, dt_bias, A_log);

    // chunked scan (NPART=2): reverse suffix-weight pass 1, forward pass 2
    scan_state_kernel<<<dim3(NPART, HH, BB * (NCH - 1)), 128>>>();
    scan_y_kernel<<<dim3(NPART, HH, BB * NCH), 128>>>();

    combine_kernel<<<ROWS, 256>>>(D_param, rms_w);

    // GEMM2: out[8192 x 256] = yg @ W_out + u
    mma_gemm_kernel<32><<<dim3(DM / 128, ROWS / 128), 256, GEMM_SMEM>>>(
        p_yh, p_yl, p_wout, out, DM, u);
}

// round 17
// speedup vs baseline: 1.2547x; 1.0508x over previous
#include <cuda_runtime.h>
#include <cuda_bf16.h>
#include <cuda_fp16.h>
#include <math.h>
#include <stdint.h>

// ---------------- problem constants ----------------
#define BB 2
#define LL 4096
#define DM 256
#define DIN 1024          // D_INNER
#define GN_ 128           // NGROUPS*D_STATE
#define HH 8              // NHEADS
#define PP 128            // HEADDIM
#define DPROJ 2312        // D_IN_PROJ (logical)
#define DPROJP 2432       // padded to 19*128
#define DCONVCH 1280      // D_INNER + 2*GN
#define ROWS (BB*LL)      // 8192
#define EPS_ 1e-5f

#define NPART 2
#define NPN 64            // n per partition (scan_state)
#define SS 8              // scan_state superstep
#define DST 4             // scan_state pipeline depth

// chunked scan
#define NCH 8
#define CLEN (LL / NCH)   // 512
#define NSUPC (CLEN / SS) // 64
#define SUB 64            // SSD sub-chunk
#define NSUB (CLEN / SUB) // 8

// ---------------- scratch (static device allocations) ----------------
__device__ __align__(16) __half g_xhh[(size_t)ROWS * DM];
__device__ __align__(16) __half g_xll[(size_t)ROWS * DM];
__device__ __align__(16) __half g_WinT[(size_t)DPROJP * DM];
__device__ __align__(16) __half g_WoutT[(size_t)DM * DIN];
__device__ __align__(16) __half g_ygh[(size_t)ROWS * DIN];
__device__ __align__(16) __half g_ygl[(size_t)ROWS * DIN];
__device__ float g_zx[(size_t)ROWS * DPROJP];
__device__ float g_xconv[(size_t)ROWS * DCONVCH];
__device__ float g_dA[(size_t)ROWS * HH];
__device__ float g_ldA[(size_t)ROWS * HH];
__device__ float g_xsh[(size_t)ROWS * PP];
__device__ float g_bh[(size_t)ROWS * HH * GN_];    // B*bscale*dt (33.5 MB)
__device__ __align__(16) __half g_y[(size_t)ROWS * DIN];   // fp16 scan output (16 MB)

typedef unsigned long long ull;
// chunk boundary states: lin = ((ch*NPART+part)*HH+h)*BB+b, ch in 0..NCH-2
__device__ __align__(16) ull g_sf[(NCH - 1) * NPART * HH * BB][32][128];
__device__ float g_aprod[(NCH - 1) * NPART * HH * BB];

// ---------------- small helpers ----------------
__device__ __forceinline__ float siluf(float x) { return x / (1.f + expf(-x)); }

__device__ __forceinline__ void split_f16(float v, __half& h, __half& l) {
    h = __float2half(v);
    l = __float2half(v - __half2float(h));
}

__device__ __forceinline__ ull f32x2_fma(ull a, ull b, ull c) {
    ull d; asm("fma.rn.f32x2 %0, %1, %2, %3;" : "=l"(d) : "l"(a), "l"(b), "l"(c)); return d;
}
__device__ __forceinline__ ull f32x2_mul(ull a, ull b) {
    ull d; asm("mul.rn.f32x2 %0, %1, %2;" : "=l"(d) : "l"(a), "l"(b)); return d;
}
__device__ __forceinline__ ull f32x2_pack(float lo, float hi) {
    ull d; asm("mov.b64 %0, {%1, %2};" : "=l"(d) : "f"(lo), "f"(hi)); return d;
}

__device__ __forceinline__ uint32_t smem_u32(const void* p) {
    uint32_t a;
    asm("{ .reg .u64 t; cvta.to.shared.u64 t, %1; cvt.u32.u64 %0, t; }" : "=r"(a) : "l"(p));
    return a;
}

// ---------------- async copy helpers ----------------
__device__ __forceinline__ void cp_async16(uint32_t saddr, const void* gptr) {
    asm volatile("cp.async.cg.shared.global [%0], [%1], 16;"
                 :: "r"(saddr), "l"(gptr) : "memory");
}
__device__ __forceinline__ void cp_async4(uint32_t saddr, const void* gptr) {
    asm volatile("cp.async.ca.shared.global [%0], [%1], 4;"
                 :: "r"(saddr), "l"(gptr) : "memory");
}
#define CP_COMMIT() asm volatile("cp.async.commit_group;" ::: "memory")
template <int N> __device__ __forceinline__ void cp_wait() {
    asm volatile("cp.async.wait_group %0;" :: "n"(N) : "memory");
}

__device__ __forceinline__ void ldmatrix_x4(uint32_t* r, uint32_t addr) {
    asm volatile("ldmatrix.sync.aligned.m8n8.x4.shared.b16 {%0,%1,%2,%3}, [%4];"
                 : "=r"(r[0]), "=r"(r[1]), "=r"(r[2]), "=r"(r[3]) : "r"(addr));
}
__device__ __forceinline__ void ldmatrix_x4t(uint32_t* r, uint32_t addr) {
    asm volatile("ldmatrix.sync.aligned.m8n8.x4.trans.shared.b16 {%0,%1,%2,%3}, [%4];"
                 : "=r"(r[0]), "=r"(r[1]), "=r"(r[2]), "=r"(r[3]) : "r"(addr));
}

__device__ __forceinline__ void mma_f16(float* c, const uint32_t* a, uint32_t b0, uint32_t b1) {
    asm volatile(
        "mma.sync.aligned.m16n8k16.row.col.f32.f16.f16.f32 "
        "{%0,%1,%2,%3}, {%4,%5,%6,%7}, {%8,%9}, {%0,%1,%2,%3};"
        : "+f"(c[0]), "+f"(c[1]), "+f"(c[2]), "+f"(c[3])
        : "r"(a[0]), "r"(a[1]), "r"(a[2]), "r"(a[3]), "r"(b0), "r"(b1));
}

// ---------------- 1) LayerNorm -> split fp16 ----------------
__global__ void ln_kernel(const float* __restrict__ u,
                          const float* __restrict__ gamma,
                          const float* __restrict__ beta) {
    __shared__ float w1[8], w2[8], bc[2];
    const int row = blockIdx.x, tid = threadIdx.x;
    const int wid = tid >> 5, lane = tid & 31;
    float v = u[(size_t)row * DM + tid];
    float s1 = v, s2 = v * v;
    #pragma unroll
    for (int o = 16; o > 0; o >>= 1) {
        s1 += __shfl_xor_sync(0xffffffffu, s1, o);
        s2 += __shfl_xor_sync(0xffffffffu, s2, o);
    }
    if (lane == 0) { w1[wid] = s1; w2[wid] = s2; }
    __syncthreads();
    if (wid == 0) {
        float a = (lane < 8) ? w1[lane] : 0.f;
        float b = (lane < 8) ? w2[lane] : 0.f;
        #pragma unroll
        for (int o = 4; o > 0; o >>= 1) {
            a += __shfl_xor_sync(0xffffffffu, a, o);
            b += __shfl_xor_sync(0xffffffffu, b, o);
        }
        if (lane == 0) {
            float mu = a * (1.f / 256.f);
            float var = b * (1.f / 256.f) - mu * mu;
            bc[0] = mu;
            bc[1] = rsqrtf(var + EPS_);
        }
    }
    __syncthreads();
    float xn = (v - bc[0]) * bc[1] * gamma[tid] + beta[tid];
    __half h, l;
    split_f16(xn, h, l);
    g_xhh[(size_t)row * DM + tid] = h;
    g_xll[(size_t)row * DM + tid] = l;
}

// ---------------- transposes of weights ----------------
__global__ void transpose_win_kernel(const float* __restrict__ W_in) {
    __shared__ float tile[32][33];
    const int tx = threadIdx.x, ty = threadIdx.y;
    const int n0 = blockIdx.x * 32, k0 = blockIdx.y * 32;
    #pragma unroll
    for (int dy = 0; dy < 32; dy += 8) {
        const int n = n0 + tx, k = k0 + ty + dy;
        tile[ty + dy][tx] = (n < DPROJ) ? W_in[(size_t)k * DPROJ + n] : 0.f;
    }
    __syncthreads();
    #pragma unroll
    for (int dy = 0; dy < 32; dy += 8) {
        const int n = n0 + ty + dy, k = k0 + tx;
        g_WinT[(size_t)n * DM + k] = __float2half(tile[tx][ty + dy]);
    }
}

__global__ void transpose_wout_kernel(const float* __restrict__ W_out) {
    __shared__ float tile[32][33];
    const int tx = threadIdx.x, ty = threadIdx.y;
    const int n0 = blockIdx.x * 32, k0 = blockIdx.y * 32;
    #pragma unroll
    for (int dy = 0; dy < 32; dy += 8) {
        tile[ty + dy][tx] = W_out[(size_t)(k0 + ty + dy) * DM + n0 + tx];
    }
    __syncthreads();
    #pragma unroll
    for (int dy = 0; dy < 32; dy += 8) {
        const int n = n0 + ty + dy, k = k0 + tx;
        g_WoutT[(size_t)n * DIN + k] = __float2half(tile[tx][ty + dy]);
    }
}

// ---------------- 2) split-fp16 GEMM (2 segments, 3-stage) ----------------
#define GSTR 40
#define ABUF (128 * GSTR * 2)
#define GEMM_SMEM (6 * ABUF)

template <int CPS>
__global__ void __launch_bounds__(256)
mma_gemm_kernel(const __half* __restrict__ Ah,
                const __half* __restrict__ Al,
                const __half* __restrict__ B,
                float* __restrict__ C, int ldc,
                const float* __restrict__ Cadd) {
    constexpr int Kin = CPS * 32;
    constexpr int T = 2 * CPS;
    extern __shared__ char dsmem[];
    const uint32_t sbase = smem_u32(dsmem);

    const int tid = threadIdx.x;
    const int wid = tid >> 5, lid = tid & 31;
    const int wm = wid >> 2;
    const int wn = wid & 3;
    const int tileRow = blockIdx.y * 128;
    const int tileCol = blockIdx.x * 128;

    const int stRow = tid >> 1;
    const int stSeg = (tid & 1) * 16;
    const uint32_t stOffB = (uint32_t)(stRow * GSTR + stSeg) * 2;

    const int aRowOff = (lid & 7) + ((lid >> 3) & 1) * 8;
    const int aKOff   = (lid >> 4) * 8;
    const int bNOff   = (lid & 7) + ((lid >> 4) & 1) * 8;
    const int bKOff   = ((lid >> 3) & 1) * 8;

    float acc[4][4][4];
    #pragma unroll
    for (int i = 0; i < 4; ++i)
        #pragma unroll
        for (int j = 0; j < 4; ++j)
            #pragma unroll
            for (int q = 0; q < 4; ++q) acc[i][j][q] = 0.f;

    auto issue = [&](int c) {
        if (c < T) {
            const int seg = c / CPS;
            const int kc = c - seg * CPS;
            const __half* Ag = seg ? Al : Ah;
            const __half* ga = Ag + (size_t)(tileRow + stRow) * Kin + kc * 32 + stSeg;
            const __half* gb = B + (size_t)(tileCol + stRow) * Kin + kc * 32 + stSeg;
            const int buf = c % 3;
            const uint32_t sa = sbase + (uint32_t)buf * ABUF + stOffB;
            const uint32_t sb = sbase + (uint32_t)(3 + buf) * ABUF + stOffB;
            cp_async16(sa, ga);
            cp_async16(sa + 16, ga + 8);
            cp_async16(sb, gb);
            cp_async16(sb + 16, gb + 8);
        }
        CP_COMMIT();
    };

    issue(0); issue(1);
    for (int c = 0; c < T; ++c) {
        cp_wait<1>();
        __syncthreads();

        const int buf = c % 3;
        const uint32_t aB = sbase + (uint32_t)buf * ABUF;
        const uint32_t bB = sbase + (uint32_t)(3 + buf) * ABUF;

        uint32_t afr[2][4][4];
        uint32_t bfr[2][2][4];
        #pragma unroll
        for (int kk2 = 0; kk2 < 2; ++kk2) {
            const int kk = kk2 * 16;
            #pragma unroll
            for (int mt = 0; mt < 4; ++mt) {
                uint32_t addr = aB + (uint32_t)((wm * 64 + mt * 16 + aRowOff) * GSTR + kk + aKOff) * 2;
                ldmatrix_x4(afr[kk2][mt], addr);
            }
            #pragma unroll
            for (int pr = 0; pr < 2; ++pr) {
                uint32_t addr = bB + (uint32_t)((wn * 32 + pr * 16 + bNOff) * GSTR + kk + bKOff) * 2;
                ldmatrix_x4(bfr[kk2][pr], addr);
            }
        }

        issue(c + 2);

        #pragma unroll
        for (int kk2 = 0; kk2 < 2; ++kk2)
            #pragma unroll
            for (int mt = 0; mt < 4; ++mt)
                #pragma unroll
                for (int nt = 0; nt < 4; ++nt) {
                    const uint32_t* bp = bfr[kk2][nt >> 1];
                    const int hi = (nt & 1) * 2;
                    mma_f16(acc[mt][nt], afr[kk2][mt], bp[hi], bp[hi + 1]);
                }
    }

    const int gID = lid >> 2, qid = lid & 3;
    #pragma unroll
    for (int mt = 0; mt < 4; ++mt) {
        const int r0 = tileRow + wm * 64 + mt * 16 + gID;
        #pragma unroll
        for (int nt = 0; nt < 4; ++nt) {
            const int col = tileCol + wn * 32 + nt * 8 + qid * 2;
            float2 v0 = make_float2(acc[mt][nt][0], acc[mt][nt][1]);
            float2 v1 = make_float2(acc[mt][nt][2], acc[mt][nt][3]);
            if (Cadd) {
                const float2 a0 = *(const float2*)(Cadd + (size_t)r0 * ldc + col);
                const float2 a1 = *(const float2*)(Cadd + (size_t)(r0 + 8) * ldc + col);
                v0.x += a0.x; v0.y += a0.y;
                v1.x += a1.x; v1.y += a1.y;
            }
            *(float2*)(C + (size_t)r0 * ldc + col) = v0;
            *(float2*)(C + (size_t)(r0 + 8) * ldc + col) = v1;
        }
    }
}

// ---------------- 3) causal depthwise conv (K=4) + SiLU ----------------
#define CLT 16
__global__ void conv_kernel(const float* __restrict__ conv_w,
                            const float* __restrict__ conv_b) {
    const int c = blockIdx.x * 256 + threadIdx.x;
    const int l0 = blockIdx.y * CLT;
    const int b = blockIdx.z;
    const size_t base = ((size_t)b * LL) * DPROJP + DIN + c;
    const float w0 = conv_w[c * 4 + 0], w1 = conv_w[c * 4 + 1];
    const float w2 = conv_w[c * 4 + 2], w3 = conv_w[c * 4 + 3];
    const float bias = conv_b[c];

    float x0 = 0.f, x1 = 0.f, x2 = 0.f;
    if (l0 > 0) {
        x0 = g_zx[base + (size_t)(l0 - 3) * DPROJP];
        x1 = g_zx[base + (size_t)(l0 - 2) * DPROJP];
        x2 = g_zx[base + (size_t)(l0 - 1) * DPROJP];
    }
    #pragma unroll
    for (int i = 0; i < CLT; ++i) {
        const float x3 = g_zx[base + (size_t)(l0 + i) * DPROJP];
        float acc = fmaf(x0, w0, bias);
        acc = fmaf(x1, w1, acc);
        acc = fmaf(x2, w2, acc);
        acc = fmaf(x3, w3, acc);
        g_xconv[((size_t)b * LL + l0 + i) * DCONVCH + c] = siluf(acc);
        x0 = x1; x1 = x2; x2 = x3;
    }
}

// ---------------- 4) prep: dt/dA/ldA + x_shared mean + prescaled B ----------------
__global__ void prep_kernel(const float* __restrict__ Bscale,
                            const float* __restrict__ dt_bias,
                            const float* __restrict__ A_log) {
    __shared__ float sdt[HH];
    const int row = blockIdx.x, p = threadIdx.x;
    if (p < HH) {
        float dt = g_zx[(size_t)row * DPROJP + 2304 + p] + dt_bias[p];
        float dtp = (dt > 20.f) ? dt : log1pf(expf(dt));
        sdt[p] = dtp;
        float la = -expf(A_log[p]) * dtp;
        g_ldA[row * HH + p] = la;
        g_dA[row * HH + p] = expf(la);
    }
    const float* xrow = g_xconv + (size_t)row * DCONVCH;
    float s = 0.f;
    #pragma unroll
    for (int h = 0; h < HH; ++h) s += xrow[h * PP + p];
    g_xsh[(size_t)row * PP + p] = s * 0.125f;
    __syncthreads();
    const float Bn = xrow[DIN + p];
    float* dst = g_bh + (size_t)row * (HH * GN_) + p;
    #pragma unroll
    for (int h = 0; h < HH; ++h)
        dst[h * GN_] = Bn * Bscale[h * GN_ + p] * sdt[h];
}

// ---------------- 5a) chunked scan pass 1: suffix-weighted state (unchanged) ----------------
#define SLOT1 200

__global__ void __launch_bounds__(128, 1)
scan_state_kernel() {
    __shared__ __align__(16) float ring[DST][SS][SLOT1];

    const int part = blockIdx.x, h = blockIdx.y;
    const int b = blockIdx.z % BB, ch = blockIdx.z / BB;
    const int tid = threadIdx.x;
    const int n0 = part * NPN;
    const int lane16 = tid & 15;
    const int tgrp = tid >> 4;
    const size_t row0 = (size_t)b * LL + (size_t)ch * CLEN;

    ull acc[32];
    #pragma unroll
    for (int j = 0; j < 32; ++j) acc[j] = 0ull;

    auto issue = [&](int s) {
        if (s >= 0 && s < NSUPC) {
            const size_t row = row0 + (size_t)s * SS + tgrp;
            float* dstT = &ring[s & (DST - 1)][tgrp][0];
            const float* bhrow  = g_bh + (row * HH + h) * GN_ + n0;
            const float* xshrow = g_xsh + row * PP;
            #pragma unroll
            for (int c = lane16; c < 48; c += 16) {
                const float* src;
                float* dst;
                if (c < 16) { src = bhrow + c * 4;         dst = dstT + c * 4; }
                else        { src = xshrow + (c - 16) * 4; dst = dstT + 64 + (c - 16) * 4; }
                cp_async16(smem_u32(dst), src);
            }
            if (lane16 == 8) cp_async4(smem_u32(dstT + 192), g_dA + row * HH + h);
        }
        CP_COMMIT();
    };

    #pragma unroll
    for (int k = 0; k < DST - 1; ++k) issue(NSUPC - 1 - k);

    float W = 1.f;
    for (int s = NSUPC - 1; s >= 0; --s) {
        cp_wait<DST - 2>();
        __syncthreads();

        const float* slotp = &ring[s & (DST - 1)][0][0];
        #pragma unroll
        for (int i = SS - 1; i >= 0; --i) {
            const float* s4 = slotp + i * SLOT1;
            const ull* s8 = (const ull*)s4;
            const float coef = W * s4[64 + tid];
            W *= s4[192];
            const ull cfp = f32x2_pack(coef, coef);
            #pragma unroll
            for (int j = 0; j < 32; ++j)
                acc[j] = f32x2_fma(cfp, s8[j], acc[j]);
        }
        issue(s - (DST - 1));
    }

    const int lin = ((ch * NPART + part) * HH + h) * BB + b;
    #pragma unroll
    for (int j = 0; j < 32; ++j) g_sf[lin][j][tid] = acc[j];
    if (tid == 0) g_aprod[lin] = W;
}

// ---------------- 5b) SSD y-pass: tensor-core chunked scan ----------------
// Per CTA (coarse chunk ch of 512, h, b): 8 sub-chunks of 64.
//   M = mask(exp(cum_t - cum_s)) ∘ (C · Bh^T)       [64x64]
//   Y = M·X + diag(e_t)·(C·S0)                      [64x128]
//   S0 <- e_last·S0 + X^T·Bh_decayed                [128x128, fp16 in smem as P[p][n]]
#define LDH 136
#define LDM 72
#define SSD_SMEM ((128*LDH + 4*64*LDH + 64*LDM) * 2 + 4 * 64 * 4)

__global__ void __launch_bounds__(256, 1)
ssd_y_kernel() {
    extern __shared__ char dsm[];
    __half* P   = (__half*)dsm;                 // [128][LDH]  state^T (p rows, n cols)
    __half* Cs  = P   + 128 * LDH;              // [64][LDH]   C rows (t x n)
    __half* Bhr = Cs  + 64 * LDH;               // [64][LDH]   bh rows (s x n)
    __half* Bhd = Bhr + 64 * LDH;               // [64][LDH]   bh * suffix-decay
    __half* Xs  = Bhd + 64 * LDH;               // [64][LDH]   x rows (s x p)
    __half* Ms  = Xs  + 64 * LDH;               // [64][LDM]   masked M (t x s)
    float* cums = (float*)(Ms + 64 * LDM);      // 64
    float* e64  = cums + 64;
    float* sd64 = e64 + 64;
    float* ldAa = sd64 + 64;

    const int ch = blockIdx.x, h = blockIdx.y, b = blockIdx.z;
    const int tid = threadIdx.x, wid = tid >> 5, lid = tid & 31;
    const int wr = wid >> 2, wc = wid & 3;
    const int gID = lid >> 2, qid = lid & 3;
    const size_t rowc = (size_t)b * LL + (size_t)ch * CLEN;

    // ---- init P from prior coarse-chunk states ----
    for (int idx = tid; idx < 128 * 128; idx += 256) {
        const int p = idx >> 7, n = idx & 127;
        float v = 0.f;
        if (ch > 0) {
            const int part = n >> 6, j = (n & 63) >> 1, el = n & 1;
            float w = 1.f;
            for (int k2 = ch - 1; k2 >= 0; --k2) {
                const int lin = ((k2 * NPART + part) * HH + h) * BB + b;
                v += w * ((const float*)&g_sf[lin][j][p])[el];
                w *= g_aprod[lin];
            }
        }
        P[p * LDH + n] = __float2half(v);
    }

    // fragment address patterns (proven, + trans recipes)
    const int aRowOff = (lid & 7) + ((lid >> 3) & 1) * 8;
    const int aKOff   = (lid >> 4) * 8;
    const int bNOff   = (lid & 7) + ((lid >> 4) & 1) * 8;
    const int bKOff   = ((lid >> 3) & 1) * 8;
    const int btK = (lid & 7) + ((lid >> 3) & 1) * 8;   // B-trans: k row
    const int btN = (lid >> 4) * 8;                      // B-trans: n col off
    const int atK = (lid & 7) + ((lid >> 4) & 1) * 8;   // A-trans: k row
    const int atM = ((lid >> 3) & 1) * 8;               // A-trans: m col off

    const uint32_t sP  = smem_u32(P);
    const uint32_t sC  = smem_u32(Cs);
    const uint32_t sBr = smem_u32(Bhr);
    const uint32_t sBd = smem_u32(Bhd);
    const uint32_t sX  = smem_u32(Xs);
    const uint32_t sM  = smem_u32(Ms);

    __syncthreads();

    for (int k = 0; k < NSUB; ++k) {
        const size_t r0 = rowc + (size_t)k * SUB;

        if (tid < 64) ldAa[tid] = g_ldA[(r0 + tid) * HH + h];
        __syncthreads();
        if (tid == 0) {
            float c = 0.f;
            for (int i = 0; i < 64; ++i) { c += ldAa[i]; cums[i] = c; }
        }
        __syncthreads();
        const float clast = cums[63];
        if (tid < 64) e64[tid] = __expf(cums[tid]);
        else if (tid < 128) sd64[tid - 64] = __expf(clast - cums[tid - 64]);

        // stage C, Bhr, X (fp32 -> fp16)
        for (int idx = tid; idx < 64 * 128; idx += 256) {
            const int s = idx >> 7, n = idx & 127;
            const size_t row = r0 + s;
            Cs[s * LDH + n]  = __float2half(g_xconv[row * DCONVCH + DIN + GN_ + n]);
            Bhr[s * LDH + n] = __float2half(g_bh[(row * HH + h) * GN_ + n]);
            Xs[s * LDH + n]  = __float2half(g_xsh[row * PP + n]);
        }
        __syncthreads();
        for (int idx = tid; idx < 64 * 128; idx += 256) {
            const int s = idx >> 7, n = idx & 127;
            Bhd[s * LDH + n] = __float2half(sd64[s] * __half2float(Bhr[s * LDH + n]));
        }

        // ---- M-GEMM: M[64t x 64s] = C · Bhr^T (K = n = 128) ----
        {
            float acc[2][2][4];
            #pragma unroll
            for (int i = 0; i < 2; ++i)
                #pragma unroll
                for (int j = 0; j < 2; ++j)
                    #pragma unroll
                    for (int q = 0; q < 4; ++q) acc[i][j][q] = 0.f;
            #pragma unroll
            for (int kk = 0; kk < 128; kk += 16) {
                uint32_t a[2][4], bb[4];
                #pragma unroll
                for (int mt = 0; mt < 2; ++mt)
                    ldmatrix_x4(a[mt], sC + (uint32_t)((wr * 32 + mt * 16 + aRowOff) * LDH + kk + aKOff) * 2);
                ldmatrix_x4(bb, sBr + (uint32_t)((wc * 16 + bNOff) * LDH + kk + bKOff) * 2);
                #pragma unroll
                for (int mt = 0; mt < 2; ++mt) {
                    mma_f16(acc[mt][0], a[mt], bb[0], bb[1]);
                    mma_f16(acc[mt][1], a[mt], bb[2], bb[3]);
                }
            }
            // mask + exp + store fp16
            #pragma unroll
            for (int mt = 0; mt < 2; ++mt)
                #pragma unroll
                for (int ns = 0; ns < 2; ++ns)
                    #pragma unroll
                    for (int q = 0; q < 4; ++q) {
                        const int t = wr * 32 + mt * 16 + gID + ((q >= 2) ? 8 : 0);
                        const int s = wc * 16 + ns * 8 + qid * 2 + (q & 1);
                        float m = (s <= t) ? acc[mt][ns][q] * __expf(cums[t] - cums[s]) : 0.f;
                        Ms[t * LDM + s] = __float2half(m);
                    }
        }
        __syncthreads();

        // ---- Y = diag(e)·(C·P^T-as-stored) + M·X ----
        {
            float acc[2][4][4];
            #pragma unroll
            for (int i = 0; i < 2; ++i)
                #pragma unroll
                for (int j = 0; j < 4; ++j)
                    #pragma unroll
                    for (int q = 0; q < 4; ++q) acc[i][j][q] = 0.f;
            // CP-GEMM: A = C [t][n], B = P [p][n] (normal), K = 128
            #pragma unroll
            for (int kk = 0; kk < 128; kk += 16) {
                uint32_t a[2][4], bb[2][4];
                #pragma unroll
                for (int mt = 0; mt < 2; ++mt)
                    ldmatrix_x4(a[mt], sC + (uint32_t)((wr * 32 + mt * 16 + aRowOff) * LDH + kk + aKOff) * 2);
                #pragma unroll
                for (int pr = 0; pr < 2; ++pr)
                    ldmatrix_x4(bb[pr], sP + (uint32_t)((wc * 32 + pr * 16 + bNOff) * LDH + kk + bKOff) * 2);
                #pragma unroll
                for (int mt = 0; mt < 2; ++mt)
                    #pragma unroll
                    for (int nt = 0; nt < 4; ++nt) {
                        const uint32_t* bp = bb[nt >> 1];
                        const int hi = (nt & 1) * 2;
                        mma_f16(acc[mt][nt], a[mt], bp[hi], bp[hi + 1]);
                    }
            }
            // scale rows by e_t
            #pragma unroll
            for (int mt = 0; mt < 2; ++mt) {
                const float e0 = e64[wr * 32 + mt * 16 + gID];
                const float e1 = e64[wr * 32 + mt * 16 + gID + 8];
                #pragma unroll
                for (int nt = 0; nt < 4; ++nt) {
                    acc[mt][nt][0] *= e0; acc[mt][nt][1] *= e0;
                    acc[mt][nt][2] *= e1; acc[mt][nt][3] *= e1;
                }
            }
            // Y-GEMM: A = Ms [t][s] normal, B = Xs [s][p] via trans, K = 64
            #pragma unroll
            for (int kk = 0; kk < 64; kk += 16) {
                uint32_t a[2][4], bb[2][4];
                #pragma unroll
                for (int mt = 0; mt < 2; ++mt)
                    ldmatrix_x4(a[mt], sM + (uint32_t)((wr * 32 + mt * 16 + aRowOff) * LDM + kk + aKOff) * 2);
                #pragma unroll
                for (int pr = 0; pr < 2; ++pr)
                    ldmatrix_x4t(bb[pr], sX + (uint32_t)((kk + btK) * LDH + wc * 32 + pr * 16 + btN) * 2);
                #pragma unroll
                for (int mt = 0; mt < 2; ++mt)
                    #pragma unroll
                    for (int nt = 0; nt < 4; ++nt) {
                        const uint32_t* bp = bb[nt >> 1];
                        const int hi = (nt & 1) * 2;
                        mma_f16(acc[mt][nt], a[mt], bp[hi], bp[hi + 1]);
                    }
            }
            // write y fp16
            #pragma unroll
            for (int mt = 0; mt < 2; ++mt) {
                const int t = wr * 32 + mt * 16 + gID;
                #pragma unroll
                for (int nt = 0; nt < 4; ++nt) {
                    const int p0 = wc * 32 + nt * 8 + qid * 2;
                    __half2 v0 = __floats2half2_rn(acc[mt][nt][0], acc[mt][nt][1]);
                    __half2 v1 = __floats2half2_rn(acc[mt][nt][2], acc[mt][nt][3]);
                    *(__half2*)(g_y + (r0 + t) * DIN + h * PP + p0) = v0;
                    *(__half2*)(g_y + (r0 + t + 8) * DIN + h * PP + p0) = v1;
                }
            }
        }
        __syncthreads();

        // ---- P update: P[p][n] = e_last·P + X^T·Bhd (K = s = 64) ----
        {
            float acc[4][4][4];
            #pragma unroll
            for (int i = 0; i < 4; ++i)
                #pragma unroll
                for (int j = 0; j < 4; ++j)
                    #pragma unroll
                    for (int q = 0; q < 4; ++q) acc[i][j][q] = 0.f;
            #pragma unroll
            for (int kk = 0; kk < 64; kk += 16) {
                uint32_t a[4][4], bb[2][4];
                #pragma unroll
                for (int mt = 0; mt < 4; ++mt)
                    ldmatrix_x4t(a[mt], sX + (uint32_t)((kk + atK) * LDH + wr * 64 + mt * 16 + atM) * 2);
                #pragma unroll
                for (int pr = 0; pr < 2; ++pr)
                    ldmatrix_x4t(bb[pr], sBd + (uint32_t)((kk + btK) * LDH + wc * 32 + pr * 16 + btN) * 2);
                #pragma unroll
                for (int mt = 0; mt < 4; ++mt)
                    #pragma unroll
                    for (int nt = 0; nt < 4; ++nt) {
                        const uint32_t* bp = bb[nt >> 1];
                        const int hi = (nt & 1) * 2;
                        mma_f16(acc[mt][nt], a[mt], bp[hi], bp[hi + 1]);
                    }
            }
            const float wl = __expf(clast);
            #pragma unroll
            for (int mt = 0; mt < 4; ++mt)
                #pragma unroll
                for (int nt = 0; nt < 4; ++nt)
                    #pragma unroll
                    for (int q = 0; q < 4; ++q) {
                        const int p = wr * 64 + mt * 16 + gID + ((q >= 2) ? 8 : 0);
                        const int n = wc * 32 + nt * 8 + qid * 2 + (q & 1);
                        __half* pp = &P[p * LDH + n];
                        *pp = __float2half(wl * __half2float(*pp) + acc[mt][nt][q]);
                    }
        }
        __syncthreads();
    }
}

// ---------------- 6) combine: y + D*x, gate, RMSNorm -> split fp16 ----------------
__global__ void combine_kernel(const float* __restrict__ D_param,
                               const float* __restrict__ rms_w) {
    const int row = blockIdx.x, tid = threadIdx.x;
    __shared__ float red[256];
    const int c0 = tid * 4;

    uint2 v = *(const uint2*)(g_y + (size_t)row * DIN + c0);
    const __half2* hp = (const __half2*)&v;
    float2 f0 = __half22float2(hp[0]);
    float2 f1 = __half22float2(hp[1]);
    float s0 = f0.x, s1 = f0.y, s2 = f1.x, s3 = f1.y;

    const float Dh = D_param[c0 >> 7];
    const float4 xs = *(const float4*)(g_xsh + (size_t)row * PP + (c0 & 127));
    s0 = fmaf(Dh, xs.x, s0); s1 = fmaf(Dh, xs.y, s1);
    s2 = fmaf(Dh, xs.z, s2); s3 = fmaf(Dh, xs.w, s3);

    const float4 z = *(const float4*)(g_zx + (size_t)row * DPROJP + c0);
    float y0 = s0 * siluf(z.x), y1 = s1 * siluf(z.y);
    float y2 = s2 * siluf(z.z), y3 = s3 * siluf(z.w);

    red[tid] = y0 * y0 + y1 * y1 + y2 * y2 + y3 * y3;
    __syncthreads();
    #pragma unroll
    for (int s = 128; s > 0; s >>= 1) { if (tid < s) red[tid] += red[tid + s]; __syncthreads(); }
    const float rstd = rsqrtf(red[0] * (1.f / (float)DIN) + EPS_);

    const float4 rw = *(const float4*)(rms_w + c0);
    float v0 = y0 * rstd * rw.x, v1 = y1 * rstd * rw.y;
    float v2 = y2 * rstd * rw.z, v3 = y3 * rstd * rw.w;

    __half hv[4], lv[4];
    split_f16(v0, hv[0], lv[0]); split_f16(v1, hv[1], lv[1]);
    split_f16(v2, hv[2], lv[2]); split_f16(v3, hv[3], lv[3]);
    *(uint2*)(g_ygh + (size_t)row * DIN + c0) = *(const uint2*)hv;
    *(uint2*)(g_ygl + (size_t)row * DIN + c0) = *(const uint2*)lv;
}

// ---------------- launch ----------------
extern "C" void kernel_launch(void* const* d_in, const int* in_sizes, int n_in,
                              void* d_out, int out_size) {
    const float* u        = (const float*)d_in[0];
    const float* ln_gamma = (const float*)d_in[1];
    const float* ln_beta  = (const float*)d_in[2];
    const float* W_in     = (const float*)d_in[3];
    const float* conv_w   = (const float*)d_in[4];
    const float* conv_b   = (const float*)d_in[5];
    const float* dt_bias  = (const float*)d_in[6];
    const float* A_log    = (const float*)d_in[7];
    const float* D_param  = (const float*)d_in[8];
    const float* B_scale  = (const float*)d_in[9];
    const float* rms_w    = (const float*)d_in[10];
    const float* W_out    = (const float*)d_in[11];
    float* out = (float*)d_out;

    cudaFuncSetAttribute(mma_gemm_kernel<8>,
                         cudaFuncAttributeMaxDynamicSharedMemorySize, GEMM_SMEM);
    cudaFuncSetAttribute(mma_gemm_kernel<32>,
                         cudaFuncAttributeMaxDynamicSharedMemorySize, GEMM_SMEM);
    cudaFuncSetAttribute(ssd_y_kernel,
                         cudaFuncAttributeMaxDynamicSharedMemorySize, SSD_SMEM);

    __half *p_xh, *p_xl, *p_win, *p_wout, *p_yh, *p_yl;
    float* p_zx;
    cudaGetSymbolAddress((void**)&p_xh, g_xhh);
    cudaGetSymbolAddress((void**)&p_xl, g_xll);
    cudaGetSymbolAddress((void**)&p_win, g_WinT);
    cudaGetSymbolAddress((void**)&p_wout, g_WoutT);
    cudaGetSymbolAddress((void**)&p_yh, g_ygh);
    cudaGetSymbolAddress((void**)&p_yl, g_ygl);
    cudaGetSymbolAddress((void**)&p_zx, g_zx);

    ln_kernel<<<ROWS, 256>>>(u, ln_gamma, ln_beta);
    transpose_win_kernel<<<dim3(DPROJP / 32, DM / 32), dim3(32, 8)>>>(W_in);
    transpose_wout_kernel<<<dim3(DM / 32, DIN / 32), dim3(32, 8)>>>(W_out);

    // GEMM1
    mma_gemm_kernel<8><<<dim3(DPROJP / 128, ROWS / 128), 256, GEMM_SMEM>>>(
        p_xh, p_xl, p_win, p_zx, DPROJP, nullptr);

    conv_kernel<<<dim3(DCONVCH / 256, LL / CLT, BB), 256>>>(conv_w, conv_b);
    prep_kernel<<<ROWS, 128>>>(B_scale, dt_bias, A_log);

    // chunked scan: scalar boundary pass + tensor-core SSD y-pass
    scan_state_kernel<<<dim3(NPART, HH, BB * (NCH - 1)), 128>>>();
    ssd_y_kernel<<<dim3(NCH, HH, BB), 256, SSD_SMEM>>>();

    combine_kernel<<<ROWS, 256>>>(D_param, rms_w);

    // GEMM2
    mma_gemm_kernel<32><<<dim3(DM / 128, ROWS / 128), 256, GEMM_SMEM>>>(
        p_yh, p_yl, p_wout, out, DM, u);
}